// round 13
// baseline (speedup 1.0000x reference)
#include <cuda_runtime.h>
#include <math.h>

#define BB 8
#define CIN 256
#define CO 64
#define VV 128
#define TT 128
#define SY 132
#define XP 136   // xs hi/lo pitch (8*cl+g bank-distinct)
#define WP 72    // weight hi/lo pitch

__device__ float g_y  [BB*CO*VV*TT];
__device__ float g_ytr[BB*TT*CO*VV];   // y_tr, later reused as OH_tr
__device__ float g_OH [BB*CO*VV*TT];
__device__ float g_OW [BB*CO*VV*TT];
__device__ float g_av [BB*CO*VV*TT];
__device__ float g_mH [BB*VV*TT];
__device__ float g_ZH [BB*VV*TT];
__device__ float g_mW [BB*VV*TT];
__device__ float g_ZW [BB*VV*TT];
__device__ float g_wtr[64*576];        // [ci][kk][o], tf32-rounded bits

typedef unsigned long long u64;

__device__ __forceinline__ float4 ld4s(const float* p){ return *reinterpret_cast<const float4*>(p); }
__device__ __forceinline__ void st4s(float* p, float4 v){ *reinterpret_cast<float4*>(p) = v; }
__device__ __forceinline__ float2 ld2f(const float* p){ return *reinterpret_cast<const float2*>(p); }
__device__ __forceinline__ float4 ld4g(const float* p){ return __ldg(reinterpret_cast<const float4*>(p)); }
__device__ __forceinline__ ulonglong2 ld2x2s(const float* p){ return *reinterpret_cast<const ulonglong2*>(p); }
__device__ __forceinline__ void st2x2s(float* p, ulonglong2 v){ *reinterpret_cast<ulonglong2*>(p) = v; }
__device__ __forceinline__ u64 pk2(float x){ u64 r; asm("mov.b64 %0,{%1,%1};" : "=l"(r) : "f"(x)); return r; }
__device__ __forceinline__ float2 up2(u64 a){ float2 f; asm("mov.b64 {%0,%1},%2;" : "=f"(f.x), "=f"(f.y) : "l"(a)); return f; }
__device__ __forceinline__ u64 fma2(u64 a, u64 b, u64 c){
    u64 d; asm("fma.rn.f32x2 %0,%1,%2,%3;" : "=l"(d) : "l"(a), "l"(b), "l"(c)); return d;
}
__device__ __forceinline__ u64 add2(u64 a, u64 b){
    u64 d; asm("add.rn.f32x2 %0,%1,%2;" : "=l"(d) : "l"(a), "l"(b)); return d;
}
__device__ __forceinline__ float dot4(float4 a, float4 b, float c){
    c = fmaf(a.x,b.x,c); c = fmaf(a.y,b.y,c); c = fmaf(a.z,b.z,c); return fmaf(a.w,b.w,c);
}
__device__ __forceinline__ unsigned tf32b(float x){
    unsigned u; asm("cvt.rna.tf32.f32 %0, %1;" : "=r"(u) : "f"(x)); return u;
}
__device__ __forceinline__ void mma_tf32(float* d, unsigned a0, unsigned a1, unsigned a2, unsigned a3,
                                         unsigned b0, unsigned b1){
    asm("mma.sync.aligned.m16n8k8.row.col.f32.tf32.tf32.f32 "
        "{%0,%1,%2,%3}, {%4,%5,%6,%7}, {%8,%9}, {%0,%1,%2,%3};"
        : "+f"(d[0]), "+f"(d[1]), "+f"(d[2]), "+f"(d[3])
        : "r"(a0), "r"(a1), "r"(a2), "r"(a3), "r"(b0), "r"(b1));
}

// ---------------- k_y: y = dc_w @ xp + dc_b via 3xtf32 MMA ----------------
// grid (128 v, 8 b), 256 threads = 8 warps (4 warpM x 2 warpN)
__global__ __launch_bounds__(256) void k_y(const float* __restrict__ x,
                                           const float* __restrict__ w,
                                           const float* __restrict__ bias) {
    __shared__ float xh[32*XP], xl[32*XP];   // [ci][t] hi/lo
    __shared__ float wh[32*WP], wl[32*WP];   // [ci][o] hi/lo
    int v = blockIdx.x, b = blockIdx.y;
    int tid = threadIdx.x, lane = tid & 31, warp = tid >> 5;
    int g = lane >> 2, cl = lane & 3;
    int warpM = warp & 3, warpN = warp >> 2;
    int m0 = warpM * 16, n0 = warpN * 64;
    bool vin = (v >= 1 && v <= 126);

    float d[8][4];
#pragma unroll
    for (int i = 0; i < 8; i++)
#pragma unroll
        for (int j = 0; j < 4; j++) d[i][j] = 0.f;

    for (int c0 = 0; c0 < CIN; c0 += 32) {
        __syncthreads();
        for (int i = tid; i < 32*128; i += 256) {
            int ci = i >> 7, t = i & 127;
            float val = 0.f;
            if (vin && t >= 1 && t <= 126)
                val = x[(((size_t)b*CIN + c0 + ci)*126 + (v-1))*126 + (t-1)];
            unsigned hb = tf32b(val);
            xh[ci*XP + t] = __uint_as_float(hb);
            xl[ci*XP + t] = __uint_as_float(tf32b(val - __uint_as_float(hb)));
        }
        for (int i = tid; i < 2048; i += 256) {
            int o = i & 63, ci = i >> 6;
            float val = __ldg(w + (size_t)o*CIN + c0 + ci);
            unsigned hb = tf32b(val);
            wh[ci*WP + o] = __uint_as_float(hb);
            wl[ci*WP + o] = __uint_as_float(tf32b(val - __uint_as_float(hb)));
        }
        __syncthreads();

        const unsigned* xhu = reinterpret_cast<const unsigned*>(xh);
        const unsigned* xlu = reinterpret_cast<const unsigned*>(xl);
        const unsigned* whu = reinterpret_cast<const unsigned*>(wh);
        const unsigned* wlu = reinterpret_cast<const unsigned*>(wl);
#pragma unroll
        for (int k0 = 0; k0 < 32; k0 += 8) {
            unsigned ah0 = whu[(k0+cl)*WP   + m0 + g];
            unsigned ah1 = whu[(k0+cl)*WP   + m0 + g + 8];
            unsigned ah2 = whu[(k0+cl+4)*WP + m0 + g];
            unsigned ah3 = whu[(k0+cl+4)*WP + m0 + g + 8];
            unsigned al0 = wlu[(k0+cl)*WP   + m0 + g];
            unsigned al1 = wlu[(k0+cl)*WP   + m0 + g + 8];
            unsigned al2 = wlu[(k0+cl+4)*WP + m0 + g];
            unsigned al3 = wlu[(k0+cl+4)*WP + m0 + g + 8];
#pragma unroll
            for (int nt = 0; nt < 8; nt++) {
                int n = n0 + nt*8 + g;
                unsigned bh0 = xhu[(k0+cl)*XP   + n];
                unsigned bh1 = xhu[(k0+cl+4)*XP + n];
                unsigned bl0 = xlu[(k0+cl)*XP   + n];
                unsigned bl1 = xlu[(k0+cl+4)*XP + n];
                mma_tf32(d[nt], ah0, ah1, ah2, ah3, bh0, bh1);
                mma_tf32(d[nt], ah0, ah1, ah2, ah3, bl0, bl1);
                mma_tf32(d[nt], al0, al1, al2, al3, bh0, bh1);
            }
        }
    }

    float bo0 = __ldg(bias + m0 + g);
    float bo1 = __ldg(bias + m0 + g + 8);
    float* dst0 = g_y + (((size_t)b*CO + m0 + g)*VV + v)*TT;
    float* dst1 = g_y + (((size_t)b*CO + m0 + g + 8)*VV + v)*TT;
#pragma unroll
    for (int nt = 0; nt < 8; nt++) {
        int t = n0 + nt*8 + 2*cl;
        *reinterpret_cast<float2*>(dst0 + t) = make_float2(d[nt][0]+bo0, d[nt][1]+bo0);
        *reinterpret_cast<float2*>(dst1 + t) = make_float2(d[nt][2]+bo1, d[nt][3]+bo1);
    }
}

// ------------- generic 128x128 transpose per (b,c) -------------
__global__ __launch_bounds__(256) void k_tr(const float* __restrict__ src,
                                            float* __restrict__ dst,
                                            int sc, int sr, int dc, int dq) {
    __shared__ float s[32][33];
    int tile = blockIdx.x, c = blockIdx.y, b = blockIdx.z;
    int r0 = (tile >> 2) * 32, q0 = (tile & 3) * 32;
    int tx = threadIdx.x, ty = threadIdx.y;
    const float* sp = src + (size_t)b*1048576 + (size_t)c*sc;
#pragma unroll
    for (int i = 0; i < 32; i += 8) s[ty+i][tx] = sp[(size_t)(r0+ty+i)*sr + q0 + tx];
    __syncthreads();
    float* dp = dst + (size_t)b*1048576 + (size_t)c*dc;
#pragma unroll
    for (int i = 0; i < 32; i += 8) dp[(size_t)(q0+ty+i)*dq + r0 + tx] = s[tx][ty+i];
}

// ---------------- weight transpose for conv: g_wtr[ci][kk][o], tf32 ----------------
__global__ __launch_bounds__(256) void k_wt(const float* __restrict__ avw) {
    int i = blockIdx.x*256 + threadIdx.x;   // < 36864
    int ci = i / 576, rem = i - ci*576;
    int kk = rem >> 6, o = rem & 63;
    float w = __ldg(avw + (size_t)o*576 + ci*9 + kk);
    g_wtr[i] = __uint_as_float(tf32b(w));
}

// ------------- spatial attention (W / H), transposed score matrix -------------
template<bool ISH>
__global__ __launch_bounds__(512, 2) void k_att(
    const float* __restrict__ qw, const float* __restrict__ qb,
    const float* __restrict__ kw, const float* __restrict__ kb,
    const float* __restrict__ vw, const float* __restrict__ vb) {
    int idx = blockIdx.x, b = blockIdx.y;
    int tid = threadIdx.x, lane = tid & 31, warp = tid >> 5, t4 = lane*4;
    extern __shared__ float sm[];
    float* E  = sm;              // E_T[s][t], 128 rows of SY
    float* ys = sm;              // alias rows 0..63 until E written
    float* qs = sm + 128*SY;     // 8 rows
    float* ks = qs + 8*SY;       // 8 rows
    float* vs = ks + 8*SY;       // 64 rows
    float* pm = qs;              // reuse after QK: partial max [4][128]
    float* pz = qs + 512;        // partial sum  [4][128]

    if (ISH) {
        const float* ysrc = g_ytr + (size_t)(b*TT + idx)*8192;
        for (int i = tid*4; i < 8192; i += 2048)
            st4s(ys + (i>>7)*SY + (i&127), ld4g(ysrc + i));
    } else {
        const float* ysrc = g_y + (size_t)b*1048576 + (size_t)idx*TT;
        for (int i = tid; i < 2048; i += 512) {
            int c = i >> 5, tt = (i & 31)*4;
            st4s(ys + c*SY + tt, ld4g(ysrc + (size_t)c*16384 + tt));
        }
    }
    __syncthreads();

    { // FUSED q/k/v projection: ONE pass over ys.
        int c4 = warp * 4;
        int which = warp >> 3, cq = warp & 7;
        const float* Wqk = which ? kw : qw;
        ulonglong2 acc[4], qa;
#pragma unroll
        for (int i = 0; i < 4; i++) { u64 bp = pk2(__ldg(vb + c4 + i)); acc[i].x = bp; acc[i].y = bp; }
        { u64 bp = pk2(__ldg((which ? kb : qb) + cq)); qa.x = bp; qa.y = bp; }
        for (int cc = 0; cc < 64; cc += 4) {
            ulonglong2 y0 = ld2x2s(ys + (cc+0)*SY + t4);
            ulonglong2 y1 = ld2x2s(ys + (cc+1)*SY + t4);
            ulonglong2 y2 = ld2x2s(ys + (cc+2)*SY + t4);
            ulonglong2 y3 = ld2x2s(ys + (cc+3)*SY + t4);
            float4 wq = ld4g(Wqk + (size_t)cq*64 + cc);
            qa.x = fma2(pk2(wq.x), y0.x, qa.x); qa.y = fma2(pk2(wq.x), y0.y, qa.y);
            qa.x = fma2(pk2(wq.y), y1.x, qa.x); qa.y = fma2(pk2(wq.y), y1.y, qa.y);
            qa.x = fma2(pk2(wq.z), y2.x, qa.x); qa.y = fma2(pk2(wq.z), y2.y, qa.y);
            qa.x = fma2(pk2(wq.w), y3.x, qa.x); qa.y = fma2(pk2(wq.w), y3.y, qa.y);
#pragma unroll
            for (int i = 0; i < 4; i++) {
                float4 wv = ld4g(vw + (size_t)(c4+i)*64 + cc);
                acc[i].x = fma2(pk2(wv.x), y0.x, acc[i].x); acc[i].y = fma2(pk2(wv.x), y0.y, acc[i].y);
                acc[i].x = fma2(pk2(wv.y), y1.x, acc[i].x); acc[i].y = fma2(pk2(wv.y), y1.y, acc[i].y);
                acc[i].x = fma2(pk2(wv.z), y2.x, acc[i].x); acc[i].y = fma2(pk2(wv.z), y2.y, acc[i].y);
                acc[i].x = fma2(pk2(wv.w), y3.x, acc[i].x); acc[i].y = fma2(pk2(wv.w), y3.y, acc[i].y);
            }
        }
#pragma unroll
        for (int i = 0; i < 4; i++) st2x2s(vs + (c4+i)*SY + t4, acc[i]);
        st2x2s((which ? ks : qs) + cq*SY + t4, qa);
    }
    __syncthreads();

    { // QK (f32x2) -> E_T[s][t] = sum_c ks[c][s]*qs[c][t]
        int s0 = (tid >> 4) * 4, t0 = (tid & 15) * 8;
        u64 acc[4][4];
#pragma unroll
        for (int i = 0; i < 4; i++)
#pragma unroll
            for (int j = 0; j < 4; j++) acc[i][j] = 0ull;
#pragma unroll
        for (int c = 0; c < 8; c++) {
            float kv[4];
#pragma unroll
            for (int i = 0; i < 4; i++) kv[i] = ks[c*SY + s0 + i];
            ulonglong2 qA = ld2x2s(qs + c*SY + t0);
            ulonglong2 qB = ld2x2s(qs + c*SY + t0 + 4);
#pragma unroll
            for (int i = 0; i < 4; i++) {
                u64 kp = pk2(kv[i]);
                acc[i][0] = fma2(kp, qA.x, acc[i][0]);
                acc[i][1] = fma2(kp, qA.y, acc[i][1]);
                acc[i][2] = fma2(kp, qB.x, acc[i][2]);
                acc[i][3] = fma2(kp, qB.y, acc[i][3]);
            }
        }
#pragma unroll
        for (int i = 0; i < 4; i++) {
            float2 p0 = up2(acc[i][0]), p1 = up2(acc[i][1]);
            float2 p2 = up2(acc[i][2]), p3 = up2(acc[i][3]);
            float vals[8] = {p0.x,p0.y,p1.x,p1.y,p2.x,p2.y,p3.x,p3.y};
            if (ISH) {
                int d = s0 + i - t0;
                if (d >= 0 && d < 8) vals[d] = -1e30f;
            }
            st4s(E + (s0+i)*SY + t0,   make_float4(vals[0],vals[1],vals[2],vals[3]));
            st4s(E + (s0+i)*SY + t0+4, make_float4(vals[4],vals[5],vals[6],vals[7]));
        }
    }
    __syncthreads();

    { // softmax over s for each column t
        int t = tid & 127, q = tid >> 7;
        int sbeg = q * 32;
        float m = -INFINITY;
#pragma unroll 8
        for (int s = sbeg; s < sbeg + 32; s++) m = fmaxf(m, E[s*SY + t]);
        pm[q*128 + t] = m;
        __syncthreads();
        float M = fmaxf(fmaxf(pm[t], pm[128+t]), fmaxf(pm[256+t], pm[384+t]));
        float Z = 0.f;
#pragma unroll 8
        for (int s = sbeg; s < sbeg + 32; s++) {
            float p = __expf(E[s*SY + t] - M);
            E[s*SY + t] = p; Z += p;
        }
        pz[q*128 + t] = Z;
        __syncthreads();
        if (q == 0) {
            float Zt = pz[t] + pz[128+t] + pz[256+t] + pz[384+t];
            if (ISH) { g_mH[((size_t)b*VV + t)*TT + idx] = M; g_ZH[((size_t)b*VV + t)*TT + idx] = Zt; }
            else     { g_mW[((size_t)b*VV + idx)*TT + t] = M; g_ZW[((size_t)b*VV + idx)*TT + t] = Zt; }
        }
    }
    __syncthreads();

    { // apply via tf32 MMA: O[ch][t] = sum_s vs[ch][s] * E[s][t]
        int warpM = warp & 3, warpN = warp >> 2;
        int m0 = warpM * 16, n0 = warpN * 32;
        int g = lane >> 2, c = lane & 3;
        float d[4][4];
#pragma unroll
        for (int nt = 0; nt < 4; nt++)
#pragma unroll
            for (int j = 0; j < 4; j++) d[nt][j] = 0.f;
#pragma unroll 4
        for (int k0 = 0; k0 < 128; k0 += 8) {
            unsigned a0 = tf32b(vs[(m0+g)*SY   + k0 + c]);
            unsigned a1 = tf32b(vs[(m0+g+8)*SY + k0 + c]);
            unsigned a2 = tf32b(vs[(m0+g)*SY   + k0 + c + 4]);
            unsigned a3 = tf32b(vs[(m0+g+8)*SY + k0 + c + 4]);
#pragma unroll
            for (int nt = 0; nt < 4; nt++) {
                unsigned b0 = tf32b(E[(k0+c)*SY   + n0 + nt*8 + g]);
                unsigned b1 = tf32b(E[(k0+c+4)*SY + n0 + nt*8 + g]);
                mma_tf32(d[nt], a0, a1, a2, a3, b0, b1);
            }
        }
        if (ISH) {
            float* dst = g_ytr + (size_t)(b*TT + idx)*8192;
#pragma unroll
            for (int nt = 0; nt < 4; nt++) {
                int t = n0 + nt*8 + 2*c;
                *reinterpret_cast<float2*>(dst + (m0+g)*128 + t)   = make_float2(d[nt][0], d[nt][1]);
                *reinterpret_cast<float2*>(dst + (m0+g+8)*128 + t) = make_float2(d[nt][2], d[nt][3]);
            }
        } else {
            float* dst = g_OW + (size_t)b*1048576 + (size_t)idx*TT;
#pragma unroll
            for (int nt = 0; nt < 4; nt++) {
                int t = n0 + nt*8 + 2*c;
                *reinterpret_cast<float2*>(dst + (size_t)(m0+g)*16384 + t)   = make_float2(d[nt][0], d[nt][1]);
                *reinterpret_cast<float2*>(dst + (size_t)(m0+g+8)*16384 + t) = make_float2(d[nt][2], d[nt][3]);
            }
        }
    }
}

// ------------- channel attention per (b,v): MMA Ec (3xtf32) + MMA M/av (tf32) -------------
__global__ __launch_bounds__(512, 2) void k_c(
    const float* __restrict__ cqw, const float* __restrict__ cqb,
    const float* __restrict__ ckw, const float* __restrict__ ckb,
    const float* __restrict__ cvw, const float* __restrict__ cvb) {
    int v = blockIdx.x, b = blockIdx.y;
    int tid = threadIdx.x, lane = tid & 31, warp = tid >> 5, t4 = lane*4;
    extern __shared__ float sm[];
    float* ys = sm;
    float* qc = sm + 64*SY;
    float* kc = sm + 128*SY;
    float* bC = sm + 192*SY;
    float* Ec = kc;              // alias (pitch 68)
    float* M  = qc;              // alias (pitch 68)
    int c4 = warp * 4;
    int g = lane >> 2, cl = lane & 3;
    int warpM = warp & 3, warpN = warp >> 2;
    int m0 = warpM * 16;

    const float* ysrc = g_y + (size_t)b*1048576 + (size_t)v*TT;
    for (int i = tid; i < 2048; i += 512) {
        int c = i >> 5, tt = (i & 31)*4;
        st4s(ys + c*SY + tt, ld4g(ysrc + (size_t)c*16384 + tt));
    }
    __syncthreads();

    { // FUSED qc+kc projection (scalar f32x2, fp32-exact)
        ulonglong2 qa[4], ka[4];
#pragma unroll
        for (int i = 0; i < 4; i++) {
            u64 bq = pk2(__ldg(cqb + c4 + i)); qa[i].x = bq; qa[i].y = bq;
            u64 bk = pk2(__ldg(ckb + c4 + i)); ka[i].x = bk; ka[i].y = bk;
        }
        for (int cc = 0; cc < 64; cc += 2) {
            ulonglong2 y0 = ld2x2s(ys + (cc+0)*SY + t4);
            ulonglong2 y1 = ld2x2s(ys + (cc+1)*SY + t4);
#pragma unroll
            for (int i = 0; i < 4; i++) {
                float2 wq = __ldg(reinterpret_cast<const float2*>(cqw + (size_t)(c4+i)*64 + cc));
                float2 wk = __ldg(reinterpret_cast<const float2*>(ckw + (size_t)(c4+i)*64 + cc));
                qa[i].x = fma2(pk2(wq.x), y0.x, qa[i].x); qa[i].y = fma2(pk2(wq.x), y0.y, qa[i].y);
                qa[i].x = fma2(pk2(wq.y), y1.x, qa[i].x); qa[i].y = fma2(pk2(wq.y), y1.y, qa[i].y);
                ka[i].x = fma2(pk2(wk.x), y0.x, ka[i].x); ka[i].y = fma2(pk2(wk.x), y0.y, ka[i].y);
                ka[i].x = fma2(pk2(wk.y), y1.x, ka[i].x); ka[i].y = fma2(pk2(wk.y), y1.y, ka[i].y);
            }
        }
#pragma unroll
        for (int i = 0; i < 4; i++) {
            st2x2s(qc + (c4+i)*SY + t4, qa[i]);
            st2x2s(kc + (c4+i)*SY + t4, ka[i]);
        }
    }
    __syncthreads();

    { // Ec[c][d] = sum_t qc[c][t]*kc[d][t] via 3xtf32 MMA
        int n0 = warpN * 16;
        float d2[2][4];
#pragma unroll
        for (int nt = 0; nt < 2; nt++)
#pragma unroll
            for (int j = 0; j < 4; j++) d2[nt][j] = 0.f;
#pragma unroll 2
        for (int k0 = 0; k0 < 128; k0 += 8) {
            float af0 = qc[(m0+g)*SY   + k0 + cl];
            float af1 = qc[(m0+g+8)*SY + k0 + cl];
            float af2 = qc[(m0+g)*SY   + k0 + cl + 4];
            float af3 = qc[(m0+g+8)*SY + k0 + cl + 4];
            unsigned ah0 = tf32b(af0), ah1 = tf32b(af1), ah2 = tf32b(af2), ah3 = tf32b(af3);
            unsigned al0 = tf32b(af0 - __uint_as_float(ah0));
            unsigned al1 = tf32b(af1 - __uint_as_float(ah1));
            unsigned al2 = tf32b(af2 - __uint_as_float(ah2));
            unsigned al3 = tf32b(af3 - __uint_as_float(ah3));
#pragma unroll
            for (int nt = 0; nt < 2; nt++) {
                float bf0 = kc[(n0 + nt*8 + g)*SY + k0 + cl];
                float bf1 = kc[(n0 + nt*8 + g)*SY + k0 + cl + 4];
                unsigned bh0 = tf32b(bf0), bh1 = tf32b(bf1);
                unsigned bl0 = tf32b(bf0 - __uint_as_float(bh0));
                unsigned bl1 = tf32b(bf1 - __uint_as_float(bh1));
                mma_tf32(d2[nt], ah0, ah1, ah2, ah3, bh0, bh1);
                mma_tf32(d2[nt], ah0, ah1, ah2, ah3, bl0, bl1);
                mma_tf32(d2[nt], al0, al1, al2, al3, bh0, bh1);
            }
        }
        __syncthreads();
#pragma unroll
        for (int nt = 0; nt < 2; nt++) {
            int dd = n0 + nt*8 + 2*cl;
            *reinterpret_cast<float2*>(Ec + (m0+g)*68 + dd)   = make_float2(d2[nt][0], d2[nt][1]);
            *reinterpret_cast<float2*>(Ec + (m0+g+8)*68 + dd) = make_float2(d2[nt][2], d2[nt][3]);
        }
    }
    __syncthreads();

    { // softmax rows of Ec (8 threads/row)
        int r = tid >> 3, sub = tid & 7;
        float* row = Ec + r*68;
        float4 x0 = ld4s(row + sub*4), x1 = ld4s(row + sub*4 + 32);
        float m = fmaxf(fmaxf(fmaxf(x0.x,x0.y),fmaxf(x0.z,x0.w)),
                        fmaxf(fmaxf(x1.x,x1.y),fmaxf(x1.z,x1.w)));
        m = fmaxf(m, __shfl_xor_sync(~0u, m, 1));
        m = fmaxf(m, __shfl_xor_sync(~0u, m, 2));
        m = fmaxf(m, __shfl_xor_sync(~0u, m, 4));
        x0.x=__expf(x0.x-m); x0.y=__expf(x0.y-m); x0.z=__expf(x0.z-m); x0.w=__expf(x0.w-m);
        x1.x=__expf(x1.x-m); x1.y=__expf(x1.y-m); x1.z=__expf(x1.z-m); x1.w=__expf(x1.w-m);
        float Z = x0.x+x0.y+x0.z+x0.w + x1.x+x1.y+x1.z+x1.w;
        Z += __shfl_xor_sync(~0u, Z, 1);
        Z += __shfl_xor_sync(~0u, Z, 2);
        Z += __shfl_xor_sync(~0u, Z, 4);
        float inv = 1.f / Z;
        x0.x*=inv; x0.y*=inv; x0.z*=inv; x0.w*=inv;
        x1.x*=inv; x1.y*=inv; x1.z*=inv; x1.w*=inv;
        st4s(row + sub*4, x0); st4s(row + sub*4 + 32, x1);
    }
    __syncthreads();

    if (tid < 64) {   // bC = attn @ cvb
        float a = 0.f;
        for (int d = 0; d < 64; d++) a = fmaf(Ec[tid*68 + d], __ldg(cvb + d), a);
        bC[tid] = a;
    }
    float dM[2][4];
    { // M[c][e] = sum_d Ec[c][d]*cvw[d][e] via tf32 MMA
        int n0 = warpN * 16;
#pragma unroll
        for (int nt = 0; nt < 2; nt++)
#pragma unroll
            for (int j = 0; j < 4; j++) dM[nt][j] = 0.f;
#pragma unroll
        for (int k0 = 0; k0 < 64; k0 += 8) {
            unsigned a0 = tf32b(Ec[(m0+g)*68   + k0 + cl]);
            unsigned a1 = tf32b(Ec[(m0+g+8)*68 + k0 + cl]);
            unsigned a2 = tf32b(Ec[(m0+g)*68   + k0 + cl + 4]);
            unsigned a3 = tf32b(Ec[(m0+g+8)*68 + k0 + cl + 4]);
#pragma unroll
            for (int nt = 0; nt < 2; nt++) {
                unsigned b0 = tf32b(__ldg(cvw + (size_t)(k0+cl)*64   + n0 + nt*8 + g));
                unsigned b1 = tf32b(__ldg(cvw + (size_t)(k0+cl+4)*64 + n0 + nt*8 + g));
                mma_tf32(dM[nt], a0, a1, a2, a3, b0, b1);
            }
        }
    }
    __syncthreads();
    {
        int n0 = warpN * 16;
#pragma unroll
        for (int nt = 0; nt < 2; nt++) {
            int e = n0 + nt*8 + 2*cl;
            *reinterpret_cast<float2*>(M + (m0+g)*68 + e)   = make_float2(dM[nt][0], dM[nt][1]);
            *reinterpret_cast<float2*>(M + (m0+g+8)*68 + e) = make_float2(dM[nt][2], dM[nt][3]);
        }
    }
    __syncthreads();

    { // av[c][t] = sum_e M[c][e]*ys[e][t] + bC[c] via tf32 MMA
        int n0 = warpN * 32;
        float d4[4][4];
        float b0v = bC[m0+g], b1v = bC[m0+g+8];
#pragma unroll
        for (int nt = 0; nt < 4; nt++) {
            d4[nt][0] = b0v; d4[nt][1] = b0v;
            d4[nt][2] = b1v; d4[nt][3] = b1v;
        }
#pragma unroll
        for (int k0 = 0; k0 < 64; k0 += 8) {
            unsigned a0 = tf32b(M[(m0+g)*68   + k0 + cl]);
            unsigned a1 = tf32b(M[(m0+g+8)*68 + k0 + cl]);
            unsigned a2 = tf32b(M[(m0+g)*68   + k0 + cl + 4]);
            unsigned a3 = tf32b(M[(m0+g+8)*68 + k0 + cl + 4]);
#pragma unroll
            for (int nt = 0; nt < 4; nt++) {
                unsigned b0 = tf32b(ys[(k0+cl)*SY   + n0 + nt*8 + g]);
                unsigned b1 = tf32b(ys[(k0+cl+4)*SY + n0 + nt*8 + g]);
                mma_tf32(d4[nt], a0, a1, a2, a3, b0, b1);
            }
        }
        float* dst = g_av + (size_t)b*1048576 + (size_t)v*TT;
#pragma unroll
        for (int nt = 0; nt < 4; nt++) {
            int t = n0 + nt*8 + 2*cl;
            *reinterpret_cast<float2*>(dst + (size_t)(m0+g)*16384 + t)   = make_float2(d4[nt][0], d4[nt][1]);
            *reinterpret_cast<float2*>(dst + (size_t)(m0+g+8)*16384 + t) = make_float2(d4[nt][2], d4[nt][3]);
        }
    }
}

// ------------- k_final: tf32 mma 3x3 conv + recombine -------------
#define AVR 20
#define AVC 360          // 18*AVR
#define CSP 260          // convS pitch (floats), multiple of 4
__global__ __launch_bounds__(256, 2) void k_final(
    const float* __restrict__ gamma_p, const float* __restrict__ sigma_p,
    float* __restrict__ out) {
    extern __shared__ float smf[];
    float* avs = smf;                 // [16 ci][18 rows][AVR]
    float* wss = smf + 16*AVC;        // [16 ci][9 kk][64 o]
    float* convS = smf;               // alias after mma: [64 o][CSP]
    float* scS = smf + 64*CSP;        // [2][256] scales
    int b = blockIdx.y, tile = blockIdx.x;
    int v0 = (tile >> 3) * 16, t0 = (tile & 7) * 16;
    int tid = threadIdx.x, lane = tid & 31, warp = tid >> 5;
    int g = lane >> 2, c = lane & 3;
    int warpM = warp >> 1, warpN = warp & 1;

    float d[16][4];
#pragma unroll
    for (int i = 0; i < 16; i++)
#pragma unroll
        for (int j = 0; j < 4; j++) d[i][j] = 0.f;

    for (int chunk = 0; chunk < 4; chunk++) {
        int ci0 = chunk * 16;
        __syncthreads();
        for (int i = tid; i < 16*324; i += 256) {
            int ci = i / 324, rr = i - ci*324;
            int r = rr / 18, cc = rr - r*18;
            int vv = v0 - 1 + r, t = t0 - 1 + cc;
            float val = 0.f;
            if (vv >= 0 && vv < 128 && t >= 0 && t < 128)
                val = g_av[(size_t)(b*64 + ci0 + ci)*16384 + (size_t)vv*128 + t];
            avs[ci*AVC + r*AVR + cc] = val;
        }
        for (int i = tid; i < 16*576; i += 256)
            wss[i] = g_wtr[ci0*576 + i];
        __syncthreads();

        const unsigned* wsu = reinterpret_cast<const unsigned*>(wss);
#pragma unroll
        for (int kk = 0; kk < 9; kk++) {
            int dv = kk / 3, dt = kk - dv*3;
#pragma unroll
            for (int ks = 0; ks < 2; ks++) {
                const unsigned* wp = wsu + (ks*8 + c)*576 + kk*64 + warpM*16 + g;
                unsigned a0 = wp[0], a1 = wp[8];
                unsigned a2 = wp[4*576], a3 = wp[4*576 + 8];
                int cb0 = (ks*8 + c)*AVC + dv*AVR + dt;
#pragma unroll
                for (int nt = 0; nt < 16; nt++) {
                    int pr = warpN*8 + (nt >> 1);
                    int pc = (nt & 1)*8 + g;
                    float f0 = avs[cb0 + pr*AVR + pc];
                    float f1 = avs[cb0 + 4*AVC + pr*AVR + pc];
                    mma_tf32(d[nt], a0, a1, a2, a3, tf32b(f0), tf32b(f1));
                }
            }
        }
    }
    __syncthreads();

#pragma unroll
    for (int nt = 0; nt < 16; nt++) {
        int pr = warpN*8 + (nt >> 1);
        int pc = (nt & 1)*8 + 2*c;
        int pix = pr*16 + pc;
        int o = warpM*16 + g;
        *reinterpret_cast<float2*>(convS + o*CSP + pix)     = make_float2(d[nt][0], d[nt][1]);
        *reinterpret_cast<float2*>(convS + (o+8)*CSP + pix) = make_float2(d[nt][2], d[nt][3]);
    }
    {
        float gamma = __ldg(gamma_p);
        int v = v0 + (tid >> 4), t = t0 + (tid & 15);
        size_t sidx = ((size_t)b*VV + v)*TT + t;
        float mH = __ldg(&g_mH[sidx]), ZH = __ldg(&g_ZH[sidx]);
        float mW = __ldg(&g_mW[sidx]), ZW = __ldg(&g_ZW[sidx]);
        float m = fmaxf(mH, mW);
        float eH = __expf(mH - m), eW = __expf(mW - m);
        float inv = gamma / (ZH*eH + ZW*eW);
        scS[tid]       = eH * inv;
        scS[256 + tid] = eW * inv;
    }
    __syncthreads();

    float sigma = __ldg(sigma_p);
    int o8 = warp * 8;
    int c4p = c * 4;
#pragma unroll
    for (int half = 0; half < 2; half++) {
        int rr = g + half*8;
        int pix = rr*16 + c4p;
        float sH0 = scS[pix],   sH1 = scS[pix+1],   sH2 = scS[pix+2],   sH3 = scS[pix+3];
        float sW0 = scS[256+pix], sW1 = scS[256+pix+1], sW2 = scS[256+pix+2], sW3 = scS[256+pix+3];
        int v = v0 + rr, t = t0 + c4p;
#pragma unroll
        for (int oi = 0; oi < 8; oi++) {
            int o = o8 + oi;
            size_t oidx = (((size_t)b*CO + o)*VV + v)*TT + t;
            float4 cv = ld4s(convS + o*CSP + pix);
            float4 yv = ld4g(&g_y[oidx]);
            float4 oh = ld4g(&g_OH[oidx]);
            float4 ow = ld4g(&g_OW[oidx]);
            float4 r;
            r.x = yv.x + sH0*oh.x + sW0*ow.x + sigma*cv.x;
            r.y = yv.y + sH1*oh.y + sW1*ow.y + sigma*cv.y;
            r.z = yv.z + sH2*oh.z + sW2*ow.z + sigma*cv.z;
            r.w = yv.w + sH3*oh.w + sW3*ow.w + sigma*cv.w;
            *reinterpret_cast<float4*>(out + oidx) = r;
        }
    }
}

// ---------------- launch: stream-parallel DAG ----------------
extern "C" void kernel_launch(void* const* d_in, const int* in_sizes, int n_in,
                              void* d_out, int out_size) {
    (void)in_sizes; (void)n_in; (void)out_size;
    const float* x    = (const float*)d_in[0];
    const float* dc_w = (const float*)d_in[1];
    const float* dc_b = (const float*)d_in[2];
    const float* q_w  = (const float*)d_in[3];
    const float* q_b  = (const float*)d_in[4];
    const float* k_w  = (const float*)d_in[5];
    const float* k_b  = (const float*)d_in[6];
    const float* v_w  = (const float*)d_in[7];
    const float* v_b  = (const float*)d_in[8];
    const float* gamma= (const float*)d_in[9];
    const float* cq_w = (const float*)d_in[10];
    const float* cq_b = (const float*)d_in[11];
    const float* ck_w = (const float*)d_in[12];
    const float* ck_b = (const float*)d_in[13];
    const float* cv_w = (const float*)d_in[14];
    const float* cv_b = (const float*)d_in[15];
    const float* av_w = (const float*)d_in[16];
    const float* sigma= (const float*)d_in[17];
    float* out = (float*)d_out;

    float *py, *pytr, *pOH;
    cudaGetSymbolAddress((void**)&py,   g_y);
    cudaGetSymbolAddress((void**)&pytr, g_ytr);
    cudaGetSymbolAddress((void**)&pOH,  g_OH);

    const int SMEM_ATT = 208*SY*4;                  // 109,824 B
    const int SMEM_C   = (192*SY + 64)*4;           // 101,632 B
    const int SMEM_F   = (64*CSP + 512)*4;          // 68,608 B

    static cudaStream_t s1 = nullptr, s2 = nullptr;
    static cudaEvent_t evy = nullptr, evw = nullptr, evc = nullptr;
    if (!s1) {
        cudaFuncSetAttribute(k_att<false>, cudaFuncAttributeMaxDynamicSharedMemorySize, SMEM_ATT);
        cudaFuncSetAttribute(k_att<true>,  cudaFuncAttributeMaxDynamicSharedMemorySize, SMEM_ATT);
        cudaFuncSetAttribute(k_c,          cudaFuncAttributeMaxDynamicSharedMemorySize, SMEM_C);
        cudaFuncSetAttribute(k_final,      cudaFuncAttributeMaxDynamicSharedMemorySize, SMEM_F);
        cudaStreamCreateWithFlags(&s1, cudaStreamNonBlocking);
        cudaStreamCreateWithFlags(&s2, cudaStreamNonBlocking);
        cudaEventCreateWithFlags(&evy, cudaEventDisableTiming);
        cudaEventCreateWithFlags(&evw, cudaEventDisableTiming);
        cudaEventCreateWithFlags(&evc, cudaEventDisableTiming);
    }

    // independent prologue on s1
    k_wt <<<144, 256, 0, s1>>>(av_w);

    // default stream: k_y, then fork
    k_y  <<<dim3(128, 8), 256>>>(x, dc_w, dc_b);
    cudaEventRecord(evy, 0);
    cudaStreamWaitEvent(s1, evy, 0);
    cudaStreamWaitEvent(s2, evy, 0);

    // s1: W-attention  |  s2: channel attention  |  default: tr -> H-attention -> tr
    k_att<false><<<dim3(128, 8), 512, SMEM_ATT, s1>>>(q_w, q_b, k_w, k_b, v_w, v_b);
    cudaEventRecord(evw, s1);
    k_c  <<<dim3(128, 8), 512, SMEM_C, s2>>>(cq_w, cq_b, ck_w, ck_b, cv_w, cv_b);
    cudaEventRecord(evc, s2);

    k_tr <<<dim3(16, 64, 8), dim3(32, 8)>>>(py, pytr, 16384, 128, 128, 8192);
    k_att<true> <<<dim3(128, 8), 512, SMEM_ATT>>>(q_w, q_b, k_w, k_b, v_w, v_b);
    k_tr <<<dim3(16, 64, 8), dim3(32, 8)>>>(pytr, pOH, 128, 8192, 16384, 128);

    // join and finish
    cudaStreamWaitEvent(0, evw, 0);
    cudaStreamWaitEvent(0, evc, 0);
    k_final<<<dim3(64, 8), 256, SMEM_F>>>(gamma, sigma, out);
}

// round 14
// speedup vs baseline: 1.1884x; 1.1884x over previous
#include <cuda_runtime.h>
#include <math.h>

#define BB 8
#define CIN 256
#define CO 64
#define VV 128
#define TT 128
#define SY 132

__device__ float g_y  [BB*CO*VV*TT];
__device__ float g_ytr[BB*TT*CO*VV];   // y_tr, later reused as OH_tr
__device__ float g_OH [BB*CO*VV*TT];
__device__ float g_OW [BB*CO*VV*TT];
__device__ float g_av [BB*CO*VV*TT];   // pre-rounded tf32 bits (written by k_c)
__device__ float g_mH [BB*VV*TT];
__device__ float g_ZH [BB*VV*TT];
__device__ float g_mW [BB*VV*TT];
__device__ float g_ZW [BB*VV*TT];
__device__ float g_wtr[64*576];        // [ci][kk][o], tf32-rounded bits
__device__ float g_cvwt[64*64];        // cvw pre-rounded tf32 bits

typedef unsigned long long u64;

__device__ __forceinline__ float4 ld4s(const float* p){ return *reinterpret_cast<const float4*>(p); }
__device__ __forceinline__ void st4s(float* p, float4 v){ *reinterpret_cast<float4*>(p) = v; }
__device__ __forceinline__ float4 ld4g(const float* p){ return __ldg(reinterpret_cast<const float4*>(p)); }
__device__ __forceinline__ ulonglong2 ld2x2s(const float* p){ return *reinterpret_cast<const ulonglong2*>(p); }
__device__ __forceinline__ void st2x2s(float* p, ulonglong2 v){ *reinterpret_cast<ulonglong2*>(p) = v; }
__device__ __forceinline__ u64 pk2(float x){ u64 r; asm("mov.b64 %0,{%1,%1};" : "=l"(r) : "f"(x)); return r; }
__device__ __forceinline__ float2 up2(u64 a){ float2 f; asm("mov.b64 {%0,%1},%2;" : "=f"(f.x), "=f"(f.y) : "l"(a)); return f; }
__device__ __forceinline__ u64 fma2(u64 a, u64 b, u64 c){
    u64 d; asm("fma.rn.f32x2 %0,%1,%2,%3;" : "=l"(d) : "l"(a), "l"(b), "l"(c)); return d;
}
__device__ __forceinline__ float dot4(float4 a, float4 b, float c){
    c = fmaf(a.x,b.x,c); c = fmaf(a.y,b.y,c); c = fmaf(a.z,b.z,c); return fmaf(a.w,b.w,c);
}
__device__ __forceinline__ unsigned tf32b(float x){
    unsigned u; asm("cvt.rna.tf32.f32 %0, %1;" : "=r"(u) : "f"(x)); return u;
}
__device__ __forceinline__ float rnd(float x){ return __uint_as_float(tf32b(x)); }
__device__ __forceinline__ unsigned fbits(float x){ return __float_as_uint(x); }
__device__ __forceinline__ void mma_tf32(float* d, unsigned a0, unsigned a1, unsigned a2, unsigned a3,
                                         unsigned b0, unsigned b1){
    asm("mma.sync.aligned.m16n8k8.row.col.f32.tf32.tf32.f32 "
        "{%0,%1,%2,%3}, {%4,%5,%6,%7}, {%8,%9}, {%0,%1,%2,%3};"
        : "+f"(d[0]), "+f"(d[1]), "+f"(d[2]), "+f"(d[3])
        : "r"(a0), "r"(a1), "r"(a2), "r"(a3), "r"(b0), "r"(b1));
}

// ---------------- k_y: y = dc_w @ xp + dc_b (R12 proven scalar) ----------------
__global__ __launch_bounds__(256) void k_y(const float* __restrict__ x,
                                           const float* __restrict__ w,
                                           const float* __restrict__ bias) {
    __shared__ float xs[32][128];
    __shared__ float wsT[32*64];   // [ci][o]
    int v = blockIdx.x, b = blockIdx.y;
    int tid = threadIdx.x, lane = tid & 31, warp = tid >> 5, t4 = lane*4;
    int o8 = warp * 8;
    ulonglong2 acc[8];
#pragma unroll
    for (int i = 0; i < 8; i++) { acc[i].x = 0ull; acc[i].y = 0ull; }
    bool vin = (v >= 1 && v <= 126);
    for (int c0 = 0; c0 < CIN; c0 += 32) {
        for (int i = tid; i < 32*128; i += 256) {
            int ci = i >> 7, t = i & 127;
            float val = 0.f;
            if (vin && t >= 1 && t <= 126)
                val = x[(((size_t)b*CIN + c0 + ci)*126 + (v-1))*126 + (t-1)];
            xs[ci][t] = val;
        }
        for (int i = tid; i < 2048; i += 256)
            wsT[i] = __ldg(w + (size_t)(i & 63)*CIN + c0 + (i >> 6));
        __syncthreads();
#pragma unroll 4
        for (int ci = 0; ci < 32; ci++) {
            ulonglong2 xv = ld2x2s(&xs[ci][t4]);
            float4 wA = ld4s(wsT + ci*64 + o8);
            float4 wB = ld4s(wsT + ci*64 + o8 + 4);
            u64 wp[8] = {pk2(wA.x),pk2(wA.y),pk2(wA.z),pk2(wA.w),
                         pk2(wB.x),pk2(wB.y),pk2(wB.z),pk2(wB.w)};
#pragma unroll
            for (int i = 0; i < 8; i++) {
                acc[i].x = fma2(wp[i], xv.x, acc[i].x);
                acc[i].y = fma2(wp[i], xv.y, acc[i].y);
            }
        }
        __syncthreads();
    }
#pragma unroll
    for (int i = 0; i < 8; i++) {
        int o = o8 + i;
        float bo = __ldg(bias + o);
        float2 lo = up2(acc[i].x);
        float2 hi = up2(acc[i].y);
        float4 r = make_float4(lo.x+bo, lo.y+bo, hi.x+bo, hi.y+bo);
        st4s(&g_y[(((size_t)b*CO + o)*VV + v)*TT + t4], r);
    }
}

// ------------- generic 128x128 transpose per (b,c) -------------
__global__ __launch_bounds__(256) void k_tr(const float* __restrict__ src,
                                            float* __restrict__ dst,
                                            int sc, int sr, int dc, int dq) {
    __shared__ float s[32][33];
    int tile = blockIdx.x, c = blockIdx.y, b = blockIdx.z;
    int r0 = (tile >> 2) * 32, q0 = (tile & 3) * 32;
    int tx = threadIdx.x, ty = threadIdx.y;
    const float* sp = src + (size_t)b*1048576 + (size_t)c*sc;
#pragma unroll
    for (int i = 0; i < 32; i += 8) s[ty+i][tx] = sp[(size_t)(r0+ty+i)*sr + q0 + tx];
    __syncthreads();
    float* dp = dst + (size_t)b*1048576 + (size_t)c*dc;
#pragma unroll
    for (int i = 0; i < 32; i += 8) dp[(size_t)(q0+ty+i)*dq + r0 + tx] = s[tx][ty+i];
}

// ---------------- weight transposes (tf32 pre-rounded) ----------------
__global__ __launch_bounds__(256) void k_wt(const float* __restrict__ avw) {
    int i = blockIdx.x*256 + threadIdx.x;   // < 36864
    int ci = i / 576, rem = i - ci*576;
    int kk = rem >> 6, o = rem & 63;
    g_wtr[i] = rnd(__ldg(avw + (size_t)o*576 + ci*9 + kk));
}
__global__ __launch_bounds__(256) void k_wv(const float* __restrict__ cvw) {
    int i = blockIdx.x*256 + threadIdx.x;   // < 4096
    g_cvwt[i] = rnd(__ldg(cvw + i));
}

// ------------- spatial attention (W / H) -------------
template<bool ISH>
__global__ __launch_bounds__(512, 2) void k_att(
    const float* __restrict__ qw, const float* __restrict__ qb,
    const float* __restrict__ kw, const float* __restrict__ kb,
    const float* __restrict__ vw, const float* __restrict__ vb) {
    int idx = blockIdx.x, b = blockIdx.y;
    int tid = threadIdx.x, lane = tid & 31, warp = tid >> 5, t4 = lane*4;
    extern __shared__ float sm[];
    float* E  = sm;              // E_T[s][t]
    float* ys = sm;              // alias rows 0..63
    float* qs = sm + 128*SY;
    float* ks = qs + 8*SY;
    float* vs = ks + 8*SY;       // stored tf32-pre-rounded
    float* pm = qs;
    float* pz = qs + 512;

    if (ISH) {
        const float* ysrc = g_ytr + (size_t)(b*TT + idx)*8192;
        for (int i = tid*4; i < 8192; i += 2048)
            st4s(ys + (i>>7)*SY + (i&127), ld4g(ysrc + i));
    } else {
        const float* ysrc = g_y + (size_t)b*1048576 + (size_t)idx*TT;
        for (int i = tid; i < 2048; i += 512) {
            int c = i >> 5, tt = (i & 31)*4;
            st4s(ys + c*SY + tt, ld4g(ysrc + (size_t)c*16384 + tt));
        }
    }
    __syncthreads();

    { // FUSED q/k/v projection: one pass over ys
        int c4 = warp * 4;
        int which = warp >> 3, cq = warp & 7;
        const float* Wqk = which ? kw : qw;
        ulonglong2 acc[4], qa;
#pragma unroll
        for (int i = 0; i < 4; i++) { u64 bp = pk2(__ldg(vb + c4 + i)); acc[i].x = bp; acc[i].y = bp; }
        { u64 bp = pk2(__ldg((which ? kb : qb) + cq)); qa.x = bp; qa.y = bp; }
        for (int cc = 0; cc < 64; cc += 4) {
            ulonglong2 y0 = ld2x2s(ys + (cc+0)*SY + t4);
            ulonglong2 y1 = ld2x2s(ys + (cc+1)*SY + t4);
            ulonglong2 y2 = ld2x2s(ys + (cc+2)*SY + t4);
            ulonglong2 y3 = ld2x2s(ys + (cc+3)*SY + t4);
            float4 wq = ld4g(Wqk + (size_t)cq*64 + cc);
            qa.x = fma2(pk2(wq.x), y0.x, qa.x); qa.y = fma2(pk2(wq.x), y0.y, qa.y);
            qa.x = fma2(pk2(wq.y), y1.x, qa.x); qa.y = fma2(pk2(wq.y), y1.y, qa.y);
            qa.x = fma2(pk2(wq.z), y2.x, qa.x); qa.y = fma2(pk2(wq.z), y2.y, qa.y);
            qa.x = fma2(pk2(wq.w), y3.x, qa.x); qa.y = fma2(pk2(wq.w), y3.y, qa.y);
#pragma unroll
            for (int i = 0; i < 4; i++) {
                float4 wv = ld4g(vw + (size_t)(c4+i)*64 + cc);
                acc[i].x = fma2(pk2(wv.x), y0.x, acc[i].x); acc[i].y = fma2(pk2(wv.x), y0.y, acc[i].y);
                acc[i].x = fma2(pk2(wv.y), y1.x, acc[i].x); acc[i].y = fma2(pk2(wv.y), y1.y, acc[i].y);
                acc[i].x = fma2(pk2(wv.z), y2.x, acc[i].x); acc[i].y = fma2(pk2(wv.z), y2.y, acc[i].y);
                acc[i].x = fma2(pk2(wv.w), y3.x, acc[i].x); acc[i].y = fma2(pk2(wv.w), y3.y, acc[i].y);
            }
        }
#pragma unroll
        for (int i = 0; i < 4; i++) {   // store vs pre-rounded to tf32 bits
            float2 lo = up2(acc[i].x), hi = up2(acc[i].y);
            st4s(vs + (c4+i)*SY + t4,
                 make_float4(rnd(lo.x), rnd(lo.y), rnd(hi.x), rnd(hi.y)));
        }
        st2x2s((which ? ks : qs) + cq*SY + t4, qa);   // q/k stay fp32-exact
    }
    __syncthreads();

    { // QK (f32x2) -> E_T[s][t]
        int s0 = (tid >> 4) * 4, t0 = (tid & 15) * 8;
        u64 acc[4][4];
#pragma unroll
        for (int i = 0; i < 4; i++)
#pragma unroll
            for (int j = 0; j < 4; j++) acc[i][j] = 0ull;
#pragma unroll
        for (int c = 0; c < 8; c++) {
            float kv[4];
#pragma unroll
            for (int i = 0; i < 4; i++) kv[i] = ks[c*SY + s0 + i];
            ulonglong2 qA = ld2x2s(qs + c*SY + t0);
            ulonglong2 qB = ld2x2s(qs + c*SY + t0 + 4);
#pragma unroll
            for (int i = 0; i < 4; i++) {
                u64 kp = pk2(kv[i]);
                acc[i][0] = fma2(kp, qA.x, acc[i][0]);
                acc[i][1] = fma2(kp, qA.y, acc[i][1]);
                acc[i][2] = fma2(kp, qB.x, acc[i][2]);
                acc[i][3] = fma2(kp, qB.y, acc[i][3]);
            }
        }
#pragma unroll
        for (int i = 0; i < 4; i++) {
            float2 p0 = up2(acc[i][0]), p1 = up2(acc[i][1]);
            float2 p2 = up2(acc[i][2]), p3 = up2(acc[i][3]);
            float vals[8] = {p0.x,p0.y,p1.x,p1.y,p2.x,p2.y,p3.x,p3.y};
            if (ISH) {
                int d = s0 + i - t0;
                if (d >= 0 && d < 8) vals[d] = -1e30f;
            }
            st4s(E + (s0+i)*SY + t0,   make_float4(vals[0],vals[1],vals[2],vals[3]));
            st4s(E + (s0+i)*SY + t0+4, make_float4(vals[4],vals[5],vals[6],vals[7]));
        }
    }
    __syncthreads();

    { // softmax over s per column t; stores PRE-ROUNDED p, Z from rounded p
        int t = tid & 127, q = tid >> 7;
        int sbeg = q * 32;
        float m = -INFINITY;
#pragma unroll 8
        for (int s = sbeg; s < sbeg + 32; s++) m = fmaxf(m, E[s*SY + t]);
        pm[q*128 + t] = m;
        __syncthreads();
        float M = fmaxf(fmaxf(pm[t], pm[128+t]), fmaxf(pm[256+t], pm[384+t]));
        float Z = 0.f;
#pragma unroll 8
        for (int s = sbeg; s < sbeg + 32; s++) {
            float p = rnd(__expf(E[s*SY + t] - M));
            E[s*SY + t] = p; Z += p;
        }
        pz[q*128 + t] = Z;
        __syncthreads();
        if (q == 0) {
            float Zt = pz[t] + pz[128+t] + pz[256+t] + pz[384+t];
            if (ISH) { g_mH[((size_t)b*VV + t)*TT + idx] = M; g_ZH[((size_t)b*VV + t)*TT + idx] = Zt; }
            else     { g_mW[((size_t)b*VV + idx)*TT + t] = M; g_ZW[((size_t)b*VV + idx)*TT + t] = Zt; }
        }
    }
    __syncthreads();

    { // apply via tf32 MMA, zero cvts (operands pre-rounded)
        int warpM = warp & 3, warpN = warp >> 2;
        int m0 = warpM * 16, n0 = warpN * 32;
        int g = lane >> 2, c = lane & 3;
        float d[4][4];
#pragma unroll
        for (int nt = 0; nt < 4; nt++)
#pragma unroll
            for (int j = 0; j < 4; j++) d[nt][j] = 0.f;
#pragma unroll 4
        for (int k0 = 0; k0 < 128; k0 += 8) {
            unsigned a0 = fbits(vs[(m0+g)*SY   + k0 + c]);
            unsigned a1 = fbits(vs[(m0+g+8)*SY + k0 + c]);
            unsigned a2 = fbits(vs[(m0+g)*SY   + k0 + c + 4]);
            unsigned a3 = fbits(vs[(m0+g+8)*SY + k0 + c + 4]);
#pragma unroll
            for (int nt = 0; nt < 4; nt++) {
                unsigned b0 = fbits(E[(k0+c)*SY   + n0 + nt*8 + g]);
                unsigned b1 = fbits(E[(k0+c+4)*SY + n0 + nt*8 + g]);
                mma_tf32(d[nt], a0, a1, a2, a3, b0, b1);
            }
        }
        if (ISH) {
            float* dst = g_ytr + (size_t)(b*TT + idx)*8192;
#pragma unroll
            for (int nt = 0; nt < 4; nt++) {
                int t = n0 + nt*8 + 2*c;
                *reinterpret_cast<float2*>(dst + (m0+g)*128 + t)   = make_float2(d[nt][0], d[nt][1]);
                *reinterpret_cast<float2*>(dst + (m0+g+8)*128 + t) = make_float2(d[nt][2], d[nt][3]);
            }
        } else {
            float* dst = g_OW + (size_t)b*1048576 + (size_t)idx*TT;
#pragma unroll
            for (int nt = 0; nt < 4; nt++) {
                int t = n0 + nt*8 + 2*c;
                *reinterpret_cast<float2*>(dst + (size_t)(m0+g)*16384 + t)   = make_float2(d[nt][0], d[nt][1]);
                *reinterpret_cast<float2*>(dst + (size_t)(m0+g+8)*16384 + t) = make_float2(d[nt][2], d[nt][3]);
            }
        }
    }
}

// ------------- channel attention per (b,v) -------------
__global__ __launch_bounds__(512, 2) void k_c(
    const float* __restrict__ cqw, const float* __restrict__ cqb,
    const float* __restrict__ ckw, const float* __restrict__ ckb,
    const float* __restrict__ cvw, const float* __restrict__ cvb) {
    int v = blockIdx.x, b = blockIdx.y;
    int tid = threadIdx.x, lane = tid & 31, warp = tid >> 5, t4 = lane*4;
    extern __shared__ float sm[];
    float* ys = sm;
    float* qc = sm + 64*SY;
    float* kc = sm + 128*SY;
    float* bC = sm + 192*SY;
    float* Ec = kc;              // alias (pitch 68)
    float* M  = qc;              // alias (pitch 68)
    int c4 = warp * 4;
    int g = lane >> 2, cl = lane & 3;
    int warpM = warp & 3, warpN = warp >> 2;
    int m0 = warpM * 16;
    (void)cvw;

    const float* ysrc = g_y + (size_t)b*1048576 + (size_t)v*TT;
    for (int i = tid; i < 2048; i += 512) {
        int c = i >> 5, tt = (i & 31)*4;
        st4s(ys + c*SY + tt, ld4g(ysrc + (size_t)c*16384 + tt));
    }
    __syncthreads();

    { // FUSED qc+kc projection (fp32-exact)
        ulonglong2 qa[4], ka[4];
#pragma unroll
        for (int i = 0; i < 4; i++) {
            u64 bq = pk2(__ldg(cqb + c4 + i)); qa[i].x = bq; qa[i].y = bq;
            u64 bk = pk2(__ldg(ckb + c4 + i)); ka[i].x = bk; ka[i].y = bk;
        }
        for (int cc = 0; cc < 64; cc += 2) {
            ulonglong2 y0 = ld2x2s(ys + (cc+0)*SY + t4);
            ulonglong2 y1 = ld2x2s(ys + (cc+1)*SY + t4);
#pragma unroll
            for (int i = 0; i < 4; i++) {
                float2 wq = __ldg(reinterpret_cast<const float2*>(cqw + (size_t)(c4+i)*64 + cc));
                float2 wk = __ldg(reinterpret_cast<const float2*>(ckw + (size_t)(c4+i)*64 + cc));
                qa[i].x = fma2(pk2(wq.x), y0.x, qa[i].x); qa[i].y = fma2(pk2(wq.x), y0.y, qa[i].y);
                qa[i].x = fma2(pk2(wq.y), y1.x, qa[i].x); qa[i].y = fma2(pk2(wq.y), y1.y, qa[i].y);
                ka[i].x = fma2(pk2(wk.x), y0.x, ka[i].x); ka[i].y = fma2(pk2(wk.x), y0.y, ka[i].y);
                ka[i].x = fma2(pk2(wk.y), y1.x, ka[i].x); ka[i].y = fma2(pk2(wk.y), y1.y, ka[i].y);
            }
        }
#pragma unroll
        for (int i = 0; i < 4; i++) {
            st2x2s(qc + (c4+i)*SY + t4, qa[i]);
            st2x2s(kc + (c4+i)*SY + t4, ka[i]);
        }
    }
    __syncthreads();

    { // Ec = qc*kc^T via 3xtf32 MMA (fp32-accurate energies)
        int n0 = warpN * 16;
        float d2[2][4];
#pragma unroll
        for (int nt = 0; nt < 2; nt++)
#pragma unroll
            for (int j = 0; j < 4; j++) d2[nt][j] = 0.f;
#pragma unroll 2
        for (int k0 = 0; k0 < 128; k0 += 8) {
            float af0 = qc[(m0+g)*SY   + k0 + cl];
            float af1 = qc[(m0+g+8)*SY + k0 + cl];
            float af2 = qc[(m0+g)*SY   + k0 + cl + 4];
            float af3 = qc[(m0+g+8)*SY + k0 + cl + 4];
            unsigned ah0 = tf32b(af0), ah1 = tf32b(af1), ah2 = tf32b(af2), ah3 = tf32b(af3);
            unsigned al0 = tf32b(af0 - __uint_as_float(ah0));
            unsigned al1 = tf32b(af1 - __uint_as_float(ah1));
            unsigned al2 = tf32b(af2 - __uint_as_float(ah2));
            unsigned al3 = tf32b(af3 - __uint_as_float(ah3));
#pragma unroll
            for (int nt = 0; nt < 2; nt++) {
                float bf0 = kc[(n0 + nt*8 + g)*SY + k0 + cl];
                float bf1 = kc[(n0 + nt*8 + g)*SY + k0 + cl + 4];
                unsigned bh0 = tf32b(bf0), bh1 = tf32b(bf1);
                unsigned bl0 = tf32b(bf0 - __uint_as_float(bh0));
                unsigned bl1 = tf32b(bf1 - __uint_as_float(bh1));
                mma_tf32(d2[nt], ah0, ah1, ah2, ah3, bh0, bh1);
                mma_tf32(d2[nt], ah0, ah1, ah2, ah3, bl0, bl1);
                mma_tf32(d2[nt], al0, al1, al2, al3, bh0, bh1);
            }
        }
        __syncthreads();
#pragma unroll
        for (int nt = 0; nt < 2; nt++) {
            int dd = n0 + nt*8 + 2*cl;
            *reinterpret_cast<float2*>(Ec + (m0+g)*68 + dd)   = make_float2(d2[nt][0], d2[nt][1]);
            *reinterpret_cast<float2*>(Ec + (m0+g+8)*68 + dd) = make_float2(d2[nt][2], d2[nt][3]);
        }
    }
    __syncthreads();

    { // softmax rows of Ec (8 threads/row); store pre-rounded weights, Z-consistent
        int r = tid >> 3, sub = tid & 7;
        float* row = Ec + r*68;
        float4 x0 = ld4s(row + sub*4), x1 = ld4s(row + sub*4 + 32);
        float m = fmaxf(fmaxf(fmaxf(x0.x,x0.y),fmaxf(x0.z,x0.w)),
                        fmaxf(fmaxf(x1.x,x1.y),fmaxf(x1.z,x1.w)));
        m = fmaxf(m, __shfl_xor_sync(~0u, m, 1));
        m = fmaxf(m, __shfl_xor_sync(~0u, m, 2));
        m = fmaxf(m, __shfl_xor_sync(~0u, m, 4));
        x0.x=__expf(x0.x-m); x0.y=__expf(x0.y-m); x0.z=__expf(x0.z-m); x0.w=__expf(x0.w-m);
        x1.x=__expf(x1.x-m); x1.y=__expf(x1.y-m); x1.z=__expf(x1.z-m); x1.w=__expf(x1.w-m);
        float Z = x0.x+x0.y+x0.z+x0.w + x1.x+x1.y+x1.z+x1.w;
        Z += __shfl_xor_sync(~0u, Z, 1);
        Z += __shfl_xor_sync(~0u, Z, 2);
        Z += __shfl_xor_sync(~0u, Z, 4);
        float inv = 1.f / Z;
        x0.x = rnd(x0.x*inv); x0.y = rnd(x0.y*inv); x0.z = rnd(x0.z*inv); x0.w = rnd(x0.w*inv);
        x1.x = rnd(x1.x*inv); x1.y = rnd(x1.y*inv); x1.z = rnd(x1.z*inv); x1.w = rnd(x1.w*inv);
        st4s(row + sub*4, x0); st4s(row + sub*4 + 32, x1);
    }
    __syncthreads();

    if (tid < 64) {   // bC = attn @ cvb
        float a = 0.f;
        for (int d = 0; d < 64; d++) a = fmaf(Ec[tid*68 + d], __ldg(cvb + d), a);
        bC[tid] = a;
    }
    float dM[2][4];
    { // M = attn @ cvw via tf32 MMA, zero cvts (attn + cvw pre-rounded)
        int n0 = warpN * 16;
#pragma unroll
        for (int nt = 0; nt < 2; nt++)
#pragma unroll
            for (int j = 0; j < 4; j++) dM[nt][j] = 0.f;
#pragma unroll
        for (int k0 = 0; k0 < 64; k0 += 8) {
            unsigned a0 = fbits(Ec[(m0+g)*68   + k0 + cl]);
            unsigned a1 = fbits(Ec[(m0+g+8)*68 + k0 + cl]);
            unsigned a2 = fbits(Ec[(m0+g)*68   + k0 + cl + 4]);
            unsigned a3 = fbits(Ec[(m0+g+8)*68 + k0 + cl + 4]);
#pragma unroll
            for (int nt = 0; nt < 2; nt++) {
                unsigned b0 = fbits(__ldg(g_cvwt + (size_t)(k0+cl)*64   + n0 + nt*8 + g));
                unsigned b1 = fbits(__ldg(g_cvwt + (size_t)(k0+cl+4)*64 + n0 + nt*8 + g));
                mma_tf32(dM[nt], a0, a1, a2, a3, b0, b1);
            }
        }
    }
    __syncthreads();
    {   // store M pre-rounded
        int n0 = warpN * 16;
#pragma unroll
        for (int nt = 0; nt < 2; nt++) {
            int e = n0 + nt*8 + 2*cl;
            *reinterpret_cast<float2*>(M + (m0+g)*68 + e)   = make_float2(rnd(dM[nt][0]), rnd(dM[nt][1]));
            *reinterpret_cast<float2*>(M + (m0+g+8)*68 + e) = make_float2(rnd(dM[nt][2]), rnd(dM[nt][3]));
        }
    }
    __syncthreads();

    { // av = M @ ys + bC via tf32 MMA (A pre-rounded; ys cvt at use); store av PRE-ROUNDED
        int n0 = warpN * 32;
        float d4[4][4];
        float b0v = bC[m0+g], b1v = bC[m0+g+8];
#pragma unroll
        for (int nt = 0; nt < 4; nt++) {
            d4[nt][0] = b0v; d4[nt][1] = b0v;
            d4[nt][2] = b1v; d4[nt][3] = b1v;
        }
#pragma unroll
        for (int k0 = 0; k0 < 64; k0 += 8) {
            unsigned a0 = fbits(M[(m0+g)*68   + k0 + cl]);
            unsigned a1 = fbits(M[(m0+g+8)*68 + k0 + cl]);
            unsigned a2 = fbits(M[(m0+g)*68   + k0 + cl + 4]);
            unsigned a3 = fbits(M[(m0+g+8)*68 + k0 + cl + 4]);
#pragma unroll
            for (int nt = 0; nt < 4; nt++) {
                unsigned b0 = tf32b(ys[(k0+cl)*SY   + n0 + nt*8 + g]);
                unsigned b1 = tf32b(ys[(k0+cl+4)*SY + n0 + nt*8 + g]);
                mma_tf32(d4[nt], a0, a1, a2, a3, b0, b1);
            }
        }
        float* dst = g_av + (size_t)b*1048576 + (size_t)v*TT;
#pragma unroll
        for (int nt = 0; nt < 4; nt++) {
            int t = n0 + nt*8 + 2*cl;
            *reinterpret_cast<float2*>(dst + (size_t)(m0+g)*16384 + t)   = make_float2(rnd(d4[nt][0]), rnd(d4[nt][1]));
            *reinterpret_cast<float2*>(dst + (size_t)(m0+g+8)*16384 + t) = make_float2(rnd(d4[nt][2]), rnd(d4[nt][3]));
        }
    }
}

// ------------- k_final: tf32 mma 3x3 conv + recombine -------------
#define AVR 20
#define AVC 360          // 18*AVR
#define CSP 260          // convS pitch, multiple of 4
__global__ __launch_bounds__(256, 2) void k_final(
    const float* __restrict__ gamma_p, const float* __restrict__ sigma_p,
    float* __restrict__ out) {
    extern __shared__ float smf[];
    float* avs = smf;                 // [16 ci][18 rows][AVR] (values pre-rounded)
    float* wss = smf + 16*AVC;        // [16 ci][9 kk][64 o]  (pre-rounded)
    float* convS = smf;               // alias after mma: [64 o][CSP]
    float* scS = smf + 64*CSP;        // [2][256] scales
    int b = blockIdx.y, tile = blockIdx.x;
    int v0 = (tile >> 3) * 16, t0 = (tile & 7) * 16;
    int tid = threadIdx.x, lane = tid & 31, warp = tid >> 5;
    int g = lane >> 2, c = lane & 3;
    int warpM = warp >> 1, warpN = warp & 1;

    float d[16][4];
#pragma unroll
    for (int i = 0; i < 16; i++)
#pragma unroll
        for (int j = 0; j < 4; j++) d[i][j] = 0.f;

    for (int chunk = 0; chunk < 4; chunk++) {
        int ci0 = chunk * 16;
        __syncthreads();
        for (int i = tid; i < 16*324; i += 256) {
            int ci = i / 324, rr = i - ci*324;
            int r = rr / 18, cc = rr - r*18;
            int vv = v0 - 1 + r, t = t0 - 1 + cc;
            float val = 0.f;
            if (vv >= 0 && vv < 128 && t >= 0 && t < 128)
                val = g_av[(size_t)(b*64 + ci0 + ci)*16384 + (size_t)vv*128 + t];
            avs[ci*AVC + r*AVR + cc] = val;
        }
        for (int i = tid; i < 16*576; i += 256)
            wss[i] = g_wtr[ci0*576 + i];
        __syncthreads();

        const unsigned* wsu = reinterpret_cast<const unsigned*>(wss);
#pragma unroll
        for (int kk = 0; kk < 9; kk++) {
            int dv = kk / 3, dt = kk - dv*3;
#pragma unroll
            for (int ks = 0; ks < 2; ks++) {
                const unsigned* wp = wsu + (ks*8 + c)*576 + kk*64 + warpM*16 + g;
                unsigned a0 = wp[0], a1 = wp[8];
                unsigned a2 = wp[4*576], a3 = wp[4*576 + 8];
                int cb0 = (ks*8 + c)*AVC + dv*AVR + dt;
#pragma unroll
                for (int nt = 0; nt < 16; nt++) {
                    int pr = warpN*8 + (nt >> 1);
                    int pc = (nt & 1)*8 + g;
                    unsigned f0 = fbits(avs[cb0 + pr*AVR + pc]);
                    unsigned f1 = fbits(avs[cb0 + 4*AVC + pr*AVR + pc]);
                    mma_tf32(d[nt], a0, a1, a2, a3, f0, f1);
                }
            }
        }
    }
    __syncthreads();

#pragma unroll
    for (int nt = 0; nt < 16; nt++) {
        int pr = warpN*8 + (nt >> 1);
        int pc = (nt & 1)*8 + 2*c;
        int pix = pr*16 + pc;
        int o = warpM*16 + g;
        *reinterpret_cast<float2*>(convS + o*CSP + pix)     = make_float2(d[nt][0], d[nt][1]);
        *reinterpret_cast<float2*>(convS + (o+8)*CSP + pix) = make_float2(d[nt][2], d[nt][3]);
    }
    {
        float gamma = __ldg(gamma_p);
        int v = v0 + (tid >> 4), t = t0 + (tid & 15);
        size_t sidx = ((size_t)b*VV + v)*TT + t;
        float mH = __ldg(&g_mH[sidx]), ZH = __ldg(&g_ZH[sidx]);
        float mW = __ldg(&g_mW[sidx]), ZW = __ldg(&g_ZW[sidx]);
        float m = fmaxf(mH, mW);
        float eH = __expf(mH - m), eW = __expf(mW - m);
        float inv = gamma / (ZH*eH + ZW*eW);
        scS[tid]       = eH * inv;
        scS[256 + tid] = eW * inv;
    }
    __syncthreads();

    float sigma = __ldg(sigma_p);
    int o8 = warp * 8;
    int c4p = c * 4;
#pragma unroll
    for (int half = 0; half < 2; half++) {
        int rr = g + half*8;
        int pix = rr*16 + c4p;
        float sH0 = scS[pix],   sH1 = scS[pix+1],   sH2 = scS[pix+2],   sH3 = scS[pix+3];
        float sW0 = scS[256+pix], sW1 = scS[256+pix+1], sW2 = scS[256+pix+2], sW3 = scS[256+pix+3];
        int v = v0 + rr, t = t0 + c4p;
#pragma unroll
        for (int oi = 0; oi < 8; oi++) {
            int o = o8 + oi;
            size_t oidx = (((size_t)b*CO + o)*VV + v)*TT + t;
            float4 cv = ld4s(convS + o*CSP + pix);
            float4 yv = ld4g(&g_y[oidx]);
            float4 oh = ld4g(&g_OH[oidx]);
            float4 ow = ld4g(&g_OW[oidx]);
            float4 r;
            r.x = yv.x + sH0*oh.x + sW0*ow.x + sigma*cv.x;
            r.y = yv.y + sH1*oh.y + sW1*ow.y + sigma*cv.y;
            r.z = yv.z + sH2*oh.z + sW2*ow.z + sigma*cv.z;
            r.w = yv.w + sH3*oh.w + sW3*ow.w + sigma*cv.w;
            *reinterpret_cast<float4*>(out + oidx) = r;
        }
    }
}

// ---------------- launch: stream-parallel DAG ----------------
extern "C" void kernel_launch(void* const* d_in, const int* in_sizes, int n_in,
                              void* d_out, int out_size) {
    (void)in_sizes; (void)n_in; (void)out_size;
    const float* x    = (const float*)d_in[0];
    const float* dc_w = (const float*)d_in[1];
    const float* dc_b = (const float*)d_in[2];
    const float* q_w  = (const float*)d_in[3];
    const float* q_b  = (const float*)d_in[4];
    const float* k_w  = (const float*)d_in[5];
    const float* k_b  = (const float*)d_in[6];
    const float* v_w  = (const float*)d_in[7];
    const float* v_b  = (const float*)d_in[8];
    const float* gamma= (const float*)d_in[9];
    const float* cq_w = (const float*)d_in[10];
    const float* cq_b = (const float*)d_in[11];
    const float* ck_w = (const float*)d_in[12];
    const float* ck_b = (const float*)d_in[13];
    const float* cv_w = (const float*)d_in[14];
    const float* cv_b = (const float*)d_in[15];
    const float* av_w = (const float*)d_in[16];
    const float* sigma= (const float*)d_in[17];
    float* out = (float*)d_out;

    float *py, *pytr, *pOH;
    cudaGetSymbolAddress((void**)&py,   g_y);
    cudaGetSymbolAddress((void**)&pytr, g_ytr);
    cudaGetSymbolAddress((void**)&pOH,  g_OH);

    const int SMEM_ATT = 208*SY*4;                  // 109,824 B
    const int SMEM_C   = (192*SY + 64)*4;           // 101,632 B
    const int SMEM_F   = (64*CSP + 512)*4;          // 68,608 B

    static cudaStream_t s1 = nullptr, s2 = nullptr;
    static cudaEvent_t evy = nullptr, evw = nullptr, evc = nullptr;
    if (!s1) {
        cudaFuncSetAttribute(k_att<false>, cudaFuncAttributeMaxDynamicSharedMemorySize, SMEM_ATT);
        cudaFuncSetAttribute(k_att<true>,  cudaFuncAttributeMaxDynamicSharedMemorySize, SMEM_ATT);
        cudaFuncSetAttribute(k_c,          cudaFuncAttributeMaxDynamicSharedMemorySize, SMEM_C);
        cudaFuncSetAttribute(k_final,      cudaFuncAttributeMaxDynamicSharedMemorySize, SMEM_F);
        cudaStreamCreateWithFlags(&s1, cudaStreamNonBlocking);
        cudaStreamCreateWithFlags(&s2, cudaStreamNonBlocking);
        cudaEventCreateWithFlags(&evy, cudaEventDisableTiming);
        cudaEventCreateWithFlags(&evw, cudaEventDisableTiming);
        cudaEventCreateWithFlags(&evc, cudaEventDisableTiming);
    }

    // independent prologue on s1
    k_wt <<<144, 256, 0, s1>>>(av_w);
    k_wv <<<16, 256, 0, s1>>>(cv_w);

    // default stream: k_y, then fork
    k_y  <<<dim3(128, 8), 256>>>(x, dc_w, dc_b);
    cudaEventRecord(evy, 0);
    cudaStreamWaitEvent(s1, evy, 0);
    cudaStreamWaitEvent(s2, evy, 0);

    // s1: W-attention  |  s2: channel attention  |  default: tr -> H-attention -> tr
    k_att<false><<<dim3(128, 8), 512, SMEM_ATT, s1>>>(q_w, q_b, k_w, k_b, v_w, v_b);
    cudaEventRecord(evw, s1);
    k_c  <<<dim3(128, 8), 512, SMEM_C, s2>>>(cq_w, cq_b, ck_w, ck_b, cv_w, cv_b);
    cudaEventRecord(evc, s2);

    k_tr <<<dim3(16, 64, 8), dim3(32, 8)>>>(py, pytr, 16384, 128, 128, 8192);
    k_att<true> <<<dim3(128, 8), 512, SMEM_ATT>>>(q_w, q_b, k_w, k_b, v_w, v_b);
    k_tr <<<dim3(16, 64, 8), dim3(32, 8)>>>(pytr, pOH, 128, 8192, 16384, 128);

    // join and finish
    cudaStreamWaitEvent(0, evw, 0);
    cudaStreamWaitEvent(0, evc, 0);
    k_final<<<dim3(64, 8), 256, SMEM_F>>>(gamma, sigma, out);
}

// round 15
// speedup vs baseline: 1.2560x; 1.0569x over previous
#include <cuda_runtime.h>
#include <math.h>

#define BB 8
#define CIN 256
#define CO 64
#define VV 128
#define TT 128
#define SY 132

__device__ float g_y  [BB*CO*VV*TT];
__device__ float g_ytr[BB*TT*CO*VV];   // y_tr, later reused as OH_tr
__device__ float g_OH [BB*CO*VV*TT];
__device__ float g_OW [BB*CO*VV*TT];
__device__ float g_av [BB*CO*VV*TT];   // pre-rounded tf32 bits (written by k_c)
__device__ float g_mH [BB*VV*TT];
__device__ float g_ZH [BB*VV*TT];
__device__ float g_mW [BB*VV*TT];
__device__ float g_ZW [BB*VV*TT];
__device__ float g_wtr[64*576];        // [ci][kk][o], tf32-rounded bits
__device__ float g_cvwt[64*64];        // cvw pre-rounded tf32 bits
__device__ float g_dwt[256*64];        // dc_w transposed [ci][o], fp32 exact

typedef unsigned long long u64;

__device__ __forceinline__ float4 ld4s(const float* p){ return *reinterpret_cast<const float4*>(p); }
__device__ __forceinline__ void st4s(float* p, float4 v){ *reinterpret_cast<float4*>(p) = v; }
__device__ __forceinline__ float4 ld4g(const float* p){ return __ldg(reinterpret_cast<const float4*>(p)); }
__device__ __forceinline__ ulonglong2 ld2x2s(const float* p){ return *reinterpret_cast<const ulonglong2*>(p); }
__device__ __forceinline__ void st2x2s(float* p, ulonglong2 v){ *reinterpret_cast<ulonglong2*>(p) = v; }
__device__ __forceinline__ u64 pk2(float x){ u64 r; asm("mov.b64 %0,{%1,%1};" : "=l"(r) : "f"(x)); return r; }
__device__ __forceinline__ float2 up2(u64 a){ float2 f; asm("mov.b64 {%0,%1},%2;" : "=f"(f.x), "=f"(f.y) : "l"(a)); return f; }
__device__ __forceinline__ u64 fma2(u64 a, u64 b, u64 c){
    u64 d; asm("fma.rn.f32x2 %0,%1,%2,%3;" : "=l"(d) : "l"(a), "l"(b), "l"(c)); return d;
}
__device__ __forceinline__ float dot4(float4 a, float4 b, float c){
    c = fmaf(a.x,b.x,c); c = fmaf(a.y,b.y,c); c = fmaf(a.z,b.z,c); return fmaf(a.w,b.w,c);
}
__device__ __forceinline__ unsigned tf32b(float x){
    unsigned u; asm("cvt.rna.tf32.f32 %0, %1;" : "=r"(u) : "f"(x)); return u;
}
__device__ __forceinline__ float rnd(float x){ return __uint_as_float(tf32b(x)); }
__device__ __forceinline__ unsigned fbits(float x){ return __float_as_uint(x); }
__device__ __forceinline__ void mma_tf32(float* d, unsigned a0, unsigned a1, unsigned a2, unsigned a3,
                                         unsigned b0, unsigned b1){
    asm("mma.sync.aligned.m16n8k8.row.col.f32.tf32.tf32.f32 "
        "{%0,%1,%2,%3}, {%4,%5,%6,%7}, {%8,%9}, {%0,%1,%2,%3};"
        : "+f"(d[0]), "+f"(d[1]), "+f"(d[2]), "+f"(d[3])
        : "r"(a0), "r"(a1), "r"(a2), "r"(a3), "r"(b0), "r"(b1));
}

// ---------------- prep: transpose dc_w -> g_dwt[ci][o] ----------------
__global__ __launch_bounds__(256) void k_wd(const float* __restrict__ w) {
    int i = blockIdx.x*256 + threadIdx.x;   // < 16384
    int ci = i >> 6, o = i & 63;
    g_dwt[i] = __ldg(w + (size_t)o*CIN + ci);
}

// ---------------- k_y: y = dc_w @ xp + dc_b ----------------
__global__ __launch_bounds__(256) void k_y(const float* __restrict__ x,
                                           const float* __restrict__ bias) {
    __shared__ float xs[32][128];
    __shared__ float wsT[32*64];   // [ci][o]
    int v = blockIdx.x, b = blockIdx.y;
    int tid = threadIdx.x, lane = tid & 31, warp = tid >> 5, t4 = lane*4;
    int o8 = warp * 8;
    ulonglong2 acc[8];
#pragma unroll
    for (int i = 0; i < 8; i++) { acc[i].x = 0ull; acc[i].y = 0ull; }
    bool vin = (v >= 1 && v <= 126);
    for (int c0 = 0; c0 < CIN; c0 += 32) {
        for (int i = tid; i < 32*128; i += 256) {
            int ci = i >> 7, t = i & 127;
            float val = 0.f;
            if (vin && t >= 1 && t <= 126)
                val = x[(((size_t)b*CIN + c0 + ci)*126 + (v-1))*126 + (t-1)];
            xs[ci][t] = val;
        }
        // coalesced contiguous copy from pre-transposed weights
        for (int i = tid; i < 512; i += 256)
            st4s(wsT + i*4, ld4g(g_dwt + c0*64 + i*4));
        __syncthreads();
#pragma unroll 4
        for (int ci = 0; ci < 32; ci++) {
            ulonglong2 xv = ld2x2s(&xs[ci][t4]);
            float4 wA = ld4s(wsT + ci*64 + o8);
            float4 wB = ld4s(wsT + ci*64 + o8 + 4);
            u64 wp[8] = {pk2(wA.x),pk2(wA.y),pk2(wA.z),pk2(wA.w),
                         pk2(wB.x),pk2(wB.y),pk2(wB.z),pk2(wB.w)};
#pragma unroll
            for (int i = 0; i < 8; i++) {
                acc[i].x = fma2(wp[i], xv.x, acc[i].x);
                acc[i].y = fma2(wp[i], xv.y, acc[i].y);
            }
        }
        __syncthreads();
    }
#pragma unroll
    for (int i = 0; i < 8; i++) {
        int o = o8 + i;
        float bo = __ldg(bias + o);
        float2 lo = up2(acc[i].x);
        float2 hi = up2(acc[i].y);
        float4 r = make_float4(lo.x+bo, lo.y+bo, hi.x+bo, hi.y+bo);
        st4s(&g_y[(((size_t)b*CO + o)*VV + v)*TT + t4], r);
    }
}

// ------------- generic 128x128 transpose per (b,c) -------------
__global__ __launch_bounds__(256) void k_tr(const float* __restrict__ src,
                                            float* __restrict__ dst,
                                            int sc, int sr, int dc, int dq) {
    __shared__ float s[32][33];
    int tile = blockIdx.x, c = blockIdx.y, b = blockIdx.z;
    int r0 = (tile >> 2) * 32, q0 = (tile & 3) * 32;
    int tx = threadIdx.x, ty = threadIdx.y;
    const float* sp = src + (size_t)b*1048576 + (size_t)c*sc;
#pragma unroll
    for (int i = 0; i < 32; i += 8) s[ty+i][tx] = sp[(size_t)(r0+ty+i)*sr + q0 + tx];
    __syncthreads();
    float* dp = dst + (size_t)b*1048576 + (size_t)c*dc;
#pragma unroll
    for (int i = 0; i < 32; i += 8) dp[(size_t)(q0+ty+i)*dq + r0 + tx] = s[tx][ty+i];
}

// ---------------- weight transposes (tf32 pre-rounded) ----------------
__global__ __launch_bounds__(256) void k_wt(const float* __restrict__ avw) {
    int i = blockIdx.x*256 + threadIdx.x;   // < 36864
    int ci = i / 576, rem = i - ci*576;
    int kk = rem >> 6, o = rem & 63;
    g_wtr[i] = rnd(__ldg(avw + (size_t)o*576 + ci*9 + kk));
}
__global__ __launch_bounds__(256) void k_wv(const float* __restrict__ cvw) {
    int i = blockIdx.x*256 + threadIdx.x;   // < 4096
    g_cvwt[i] = rnd(__ldg(cvw + i));
}

// ------------- spatial attention (W / H) -------------
template<bool ISH>
__global__ __launch_bounds__(512, 2) void k_att(
    const float* __restrict__ qw, const float* __restrict__ qb,
    const float* __restrict__ kw, const float* __restrict__ kb,
    const float* __restrict__ vw, const float* __restrict__ vb) {
    int idx = blockIdx.x, b = blockIdx.y;
    int tid = threadIdx.x, lane = tid & 31, warp = tid >> 5, t4 = lane*4;
    extern __shared__ float sm[];
    float* E  = sm;              // E_T[s][t]
    float* ys = sm;              // alias rows 0..63
    float* qs = sm + 128*SY;
    float* ks = qs + 8*SY;
    float* vs = ks + 8*SY;       // stored tf32-pre-rounded
    float* pm = qs;
    float* pz = qs + 512;

    if (ISH) {
        const float* ysrc = g_ytr + (size_t)(b*TT + idx)*8192;
        for (int i = tid*4; i < 8192; i += 2048)
            st4s(ys + (i>>7)*SY + (i&127), ld4g(ysrc + i));
    } else {
        const float* ysrc = g_y + (size_t)b*1048576 + (size_t)idx*TT;
        for (int i = tid; i < 2048; i += 512) {
            int c = i >> 5, tt = (i & 31)*4;
            st4s(ys + c*SY + tt, ld4g(ysrc + (size_t)c*16384 + tt));
        }
    }
    __syncthreads();

    { // FUSED q/k/v projection: one pass over ys
        int c4 = warp * 4;
        int which = warp >> 3, cq = warp & 7;
        const float* Wqk = which ? kw : qw;
        ulonglong2 acc[4], qa;
#pragma unroll
        for (int i = 0; i < 4; i++) { u64 bp = pk2(__ldg(vb + c4 + i)); acc[i].x = bp; acc[i].y = bp; }
        { u64 bp = pk2(__ldg((which ? kb : qb) + cq)); qa.x = bp; qa.y = bp; }
#pragma unroll 2
        for (int cc = 0; cc < 64; cc += 4) {
            ulonglong2 y0 = ld2x2s(ys + (cc+0)*SY + t4);
            ulonglong2 y1 = ld2x2s(ys + (cc+1)*SY + t4);
            ulonglong2 y2 = ld2x2s(ys + (cc+2)*SY + t4);
            ulonglong2 y3 = ld2x2s(ys + (cc+3)*SY + t4);
            float4 wq = ld4g(Wqk + (size_t)cq*64 + cc);
            qa.x = fma2(pk2(wq.x), y0.x, qa.x); qa.y = fma2(pk2(wq.x), y0.y, qa.y);
            qa.x = fma2(pk2(wq.y), y1.x, qa.x); qa.y = fma2(pk2(wq.y), y1.y, qa.y);
            qa.x = fma2(pk2(wq.z), y2.x, qa.x); qa.y = fma2(pk2(wq.z), y2.y, qa.y);
            qa.x = fma2(pk2(wq.w), y3.x, qa.x); qa.y = fma2(pk2(wq.w), y3.y, qa.y);
#pragma unroll
            for (int i = 0; i < 4; i++) {
                float4 wv = ld4g(vw + (size_t)(c4+i)*64 + cc);
                acc[i].x = fma2(pk2(wv.x), y0.x, acc[i].x); acc[i].y = fma2(pk2(wv.x), y0.y, acc[i].y);
                acc[i].x = fma2(pk2(wv.y), y1.x, acc[i].x); acc[i].y = fma2(pk2(wv.y), y1.y, acc[i].y);
                acc[i].x = fma2(pk2(wv.z), y2.x, acc[i].x); acc[i].y = fma2(pk2(wv.z), y2.y, acc[i].y);
                acc[i].x = fma2(pk2(wv.w), y3.x, acc[i].x); acc[i].y = fma2(pk2(wv.w), y3.y, acc[i].y);
            }
        }
#pragma unroll
        for (int i = 0; i < 4; i++) {   // store vs pre-rounded to tf32 bits
            float2 lo = up2(acc[i].x), hi = up2(acc[i].y);
            st4s(vs + (c4+i)*SY + t4,
                 make_float4(rnd(lo.x), rnd(lo.y), rnd(hi.x), rnd(hi.y)));
        }
        st2x2s((which ? ks : qs) + cq*SY + t4, qa);   // q/k stay fp32-exact
    }
    __syncthreads();

    { // QK (f32x2) -> E_T[s][t]
        int s0 = (tid >> 4) * 4, t0 = (tid & 15) * 8;
        u64 acc[4][4];
#pragma unroll
        for (int i = 0; i < 4; i++)
#pragma unroll
            for (int j = 0; j < 4; j++) acc[i][j] = 0ull;
#pragma unroll
        for (int c = 0; c < 8; c++) {
            float kv[4];
#pragma unroll
            for (int i = 0; i < 4; i++) kv[i] = ks[c*SY + s0 + i];
            ulonglong2 qA = ld2x2s(qs + c*SY + t0);
            ulonglong2 qB = ld2x2s(qs + c*SY + t0 + 4);
#pragma unroll
            for (int i = 0; i < 4; i++) {
                u64 kp = pk2(kv[i]);
                acc[i][0] = fma2(kp, qA.x, acc[i][0]);
                acc[i][1] = fma2(kp, qA.y, acc[i][1]);
                acc[i][2] = fma2(kp, qB.x, acc[i][2]);
                acc[i][3] = fma2(kp, qB.y, acc[i][3]);
            }
        }
#pragma unroll
        for (int i = 0; i < 4; i++) {
            float2 p0 = up2(acc[i][0]), p1 = up2(acc[i][1]);
            float2 p2 = up2(acc[i][2]), p3 = up2(acc[i][3]);
            float vals[8] = {p0.x,p0.y,p1.x,p1.y,p2.x,p2.y,p3.x,p3.y};
            if (ISH) {
                int d = s0 + i - t0;
                if (d >= 0 && d < 8) vals[d] = -1e30f;
            }
            st4s(E + (s0+i)*SY + t0,   make_float4(vals[0],vals[1],vals[2],vals[3]));
            st4s(E + (s0+i)*SY + t0+4, make_float4(vals[4],vals[5],vals[6],vals[7]));
        }
    }
    __syncthreads();

    { // softmax over s per column t; stores PRE-ROUNDED p, Z from rounded p
        int t = tid & 127, q = tid >> 7;
        int sbeg = q * 32;
        float m = -INFINITY;
#pragma unroll 8
        for (int s = sbeg; s < sbeg + 32; s++) m = fmaxf(m, E[s*SY + t]);
        pm[q*128 + t] = m;
        __syncthreads();
        float M = fmaxf(fmaxf(pm[t], pm[128+t]), fmaxf(pm[256+t], pm[384+t]));
        float Z = 0.f;
#pragma unroll 8
        for (int s = sbeg; s < sbeg + 32; s++) {
            float p = rnd(__expf(E[s*SY + t] - M));
            E[s*SY + t] = p; Z += p;
        }
        pz[q*128 + t] = Z;
        __syncthreads();
        if (q == 0) {
            float Zt = pz[t] + pz[128+t] + pz[256+t] + pz[384+t];
            if (ISH) { g_mH[((size_t)b*VV + t)*TT + idx] = M; g_ZH[((size_t)b*VV + t)*TT + idx] = Zt; }
            else     { g_mW[((size_t)b*VV + idx)*TT + t] = M; g_ZW[((size_t)b*VV + idx)*TT + t] = Zt; }
        }
    }
    __syncthreads();

    { // apply via tf32 MMA, zero cvts (operands pre-rounded)
        int warpM = warp & 3, warpN = warp >> 2;
        int m0 = warpM * 16, n0 = warpN * 32;
        int g = lane >> 2, c = lane & 3;
        float d[4][4];
#pragma unroll
        for (int nt = 0; nt < 4; nt++)
#pragma unroll
            for (int j = 0; j < 4; j++) d[nt][j] = 0.f;
#pragma unroll 4
        for (int k0 = 0; k0 < 128; k0 += 8) {
            unsigned a0 = fbits(vs[(m0+g)*SY   + k0 + c]);
            unsigned a1 = fbits(vs[(m0+g+8)*SY + k0 + c]);
            unsigned a2 = fbits(vs[(m0+g)*SY   + k0 + c + 4]);
            unsigned a3 = fbits(vs[(m0+g+8)*SY + k0 + c + 4]);
#pragma unroll
            for (int nt = 0; nt < 4; nt++) {
                unsigned b0 = fbits(E[(k0+c)*SY   + n0 + nt*8 + g]);
                unsigned b1 = fbits(E[(k0+c+4)*SY + n0 + nt*8 + g]);
                mma_tf32(d[nt], a0, a1, a2, a3, b0, b1);
            }
        }
        if (ISH) {
            float* dst = g_ytr + (size_t)(b*TT + idx)*8192;
#pragma unroll
            for (int nt = 0; nt < 4; nt++) {
                int t = n0 + nt*8 + 2*c;
                *reinterpret_cast<float2*>(dst + (m0+g)*128 + t)   = make_float2(d[nt][0], d[nt][1]);
                *reinterpret_cast<float2*>(dst + (m0+g+8)*128 + t) = make_float2(d[nt][2], d[nt][3]);
            }
        } else {
            float* dst = g_OW + (size_t)b*1048576 + (size_t)idx*TT;
#pragma unroll
            for (int nt = 0; nt < 4; nt++) {
                int t = n0 + nt*8 + 2*c;
                *reinterpret_cast<float2*>(dst + (size_t)(m0+g)*16384 + t)   = make_float2(d[nt][0], d[nt][1]);
                *reinterpret_cast<float2*>(dst + (size_t)(m0+g+8)*16384 + t) = make_float2(d[nt][2], d[nt][3]);
            }
        }
    }
}

// ------------- channel attention per (b,v) -------------
__global__ __launch_bounds__(512, 2) void k_c(
    const float* __restrict__ cqw, const float* __restrict__ cqb,
    const float* __restrict__ ckw, const float* __restrict__ ckb,
    const float* __restrict__ cvb) {
    int v = blockIdx.x, b = blockIdx.y;
    int tid = threadIdx.x, lane = tid & 31, warp = tid >> 5, t4 = lane*4;
    extern __shared__ float sm[];
    float* ys = sm;
    float* qc = sm + 64*SY;
    float* kc = sm + 128*SY;
    float* bC = sm + 192*SY;
    float* Ec = kc;              // alias (pitch 68)
    float* M  = qc;              // alias (pitch 68)
    int c4 = warp * 4;
    int g = lane >> 2, cl = lane & 3;
    int warpM = warp & 3, warpN = warp >> 2;
    int m0 = warpM * 16;

    const float* ysrc = g_y + (size_t)b*1048576 + (size_t)v*TT;
    for (int i = tid; i < 2048; i += 512) {
        int c = i >> 5, tt = (i & 31)*4;
        st4s(ys + c*SY + tt, ld4g(ysrc + (size_t)c*16384 + tt));
    }
    __syncthreads();

    { // FUSED qc+kc projection (fp32-exact)
        ulonglong2 qa[4], ka[4];
#pragma unroll
        for (int i = 0; i < 4; i++) {
            u64 bq = pk2(__ldg(cqb + c4 + i)); qa[i].x = bq; qa[i].y = bq;
            u64 bk = pk2(__ldg(ckb + c4 + i)); ka[i].x = bk; ka[i].y = bk;
        }
#pragma unroll 2
        for (int cc = 0; cc < 64; cc += 2) {
            ulonglong2 y0 = ld2x2s(ys + (cc+0)*SY + t4);
            ulonglong2 y1 = ld2x2s(ys + (cc+1)*SY + t4);
#pragma unroll
            for (int i = 0; i < 4; i++) {
                float2 wq = __ldg(reinterpret_cast<const float2*>(cqw + (size_t)(c4+i)*64 + cc));
                float2 wk = __ldg(reinterpret_cast<const float2*>(ckw + (size_t)(c4+i)*64 + cc));
                qa[i].x = fma2(pk2(wq.x), y0.x, qa[i].x); qa[i].y = fma2(pk2(wq.x), y0.y, qa[i].y);
                qa[i].x = fma2(pk2(wq.y), y1.x, qa[i].x); qa[i].y = fma2(pk2(wq.y), y1.y, qa[i].y);
                ka[i].x = fma2(pk2(wk.x), y0.x, ka[i].x); ka[i].y = fma2(pk2(wk.x), y0.y, ka[i].y);
                ka[i].x = fma2(pk2(wk.y), y1.x, ka[i].x); ka[i].y = fma2(pk2(wk.y), y1.y, ka[i].y);
            }
        }
#pragma unroll
        for (int i = 0; i < 4; i++) {
            st2x2s(qc + (c4+i)*SY + t4, qa[i]);
            st2x2s(kc + (c4+i)*SY + t4, ka[i]);
        }
    }
    __syncthreads();

    { // Ec = qc*kc^T via 3xtf32 MMA (fp32-accurate energies)
        int n0 = warpN * 16;
        float d2[2][4];
#pragma unroll
        for (int nt = 0; nt < 2; nt++)
#pragma unroll
            for (int j = 0; j < 4; j++) d2[nt][j] = 0.f;
#pragma unroll 2
        for (int k0 = 0; k0 < 128; k0 += 8) {
            float af0 = qc[(m0+g)*SY   + k0 + cl];
            float af1 = qc[(m0+g+8)*SY + k0 + cl];
            float af2 = qc[(m0+g)*SY   + k0 + cl + 4];
            float af3 = qc[(m0+g+8)*SY + k0 + cl + 4];
            unsigned ah0 = tf32b(af0), ah1 = tf32b(af1), ah2 = tf32b(af2), ah3 = tf32b(af3);
            unsigned al0 = tf32b(af0 - __uint_as_float(ah0));
            unsigned al1 = tf32b(af1 - __uint_as_float(ah1));
            unsigned al2 = tf32b(af2 - __uint_as_float(ah2));
            unsigned al3 = tf32b(af3 - __uint_as_float(ah3));
#pragma unroll
            for (int nt = 0; nt < 2; nt++) {
                float bf0 = kc[(n0 + nt*8 + g)*SY + k0 + cl];
                float bf1 = kc[(n0 + nt*8 + g)*SY + k0 + cl + 4];
                unsigned bh0 = tf32b(bf0), bh1 = tf32b(bf1);
                unsigned bl0 = tf32b(bf0 - __uint_as_float(bh0));
                unsigned bl1 = tf32b(bf1 - __uint_as_float(bh1));
                mma_tf32(d2[nt], ah0, ah1, ah2, ah3, bh0, bh1);
                mma_tf32(d2[nt], ah0, ah1, ah2, ah3, bl0, bl1);
                mma_tf32(d2[nt], al0, al1, al2, al3, bh0, bh1);
            }
        }
        __syncthreads();
#pragma unroll
        for (int nt = 0; nt < 2; nt++) {
            int dd = n0 + nt*8 + 2*cl;
            *reinterpret_cast<float2*>(Ec + (m0+g)*68 + dd)   = make_float2(d2[nt][0], d2[nt][1]);
            *reinterpret_cast<float2*>(Ec + (m0+g+8)*68 + dd) = make_float2(d2[nt][2], d2[nt][3]);
        }
    }
    __syncthreads();

    { // softmax rows of Ec (8 threads/row); store pre-rounded weights
        int r = tid >> 3, sub = tid & 7;
        float* row = Ec + r*68;
        float4 x0 = ld4s(row + sub*4), x1 = ld4s(row + sub*4 + 32);
        float m = fmaxf(fmaxf(fmaxf(x0.x,x0.y),fmaxf(x0.z,x0.w)),
                        fmaxf(fmaxf(x1.x,x1.y),fmaxf(x1.z,x1.w)));
        m = fmaxf(m, __shfl_xor_sync(~0u, m, 1));
        m = fmaxf(m, __shfl_xor_sync(~0u, m, 2));
        m = fmaxf(m, __shfl_xor_sync(~0u, m, 4));
        x0.x=__expf(x0.x-m); x0.y=__expf(x0.y-m); x0.z=__expf(x0.z-m); x0.w=__expf(x0.w-m);
        x1.x=__expf(x1.x-m); x1.y=__expf(x1.y-m); x1.z=__expf(x1.z-m); x1.w=__expf(x1.w-m);
        float Z = x0.x+x0.y+x0.z+x0.w + x1.x+x1.y+x1.z+x1.w;
        Z += __shfl_xor_sync(~0u, Z, 1);
        Z += __shfl_xor_sync(~0u, Z, 2);
        Z += __shfl_xor_sync(~0u, Z, 4);
        float inv = 1.f / Z;
        x0.x = rnd(x0.x*inv); x0.y = rnd(x0.y*inv); x0.z = rnd(x0.z*inv); x0.w = rnd(x0.w*inv);
        x1.x = rnd(x1.x*inv); x1.y = rnd(x1.y*inv); x1.z = rnd(x1.z*inv); x1.w = rnd(x1.w*inv);
        st4s(row + sub*4, x0); st4s(row + sub*4 + 32, x1);
    }
    __syncthreads();

    if (tid < 64) {   // bC = attn @ cvb
        float a = 0.f;
        for (int d = 0; d < 64; d++) a = fmaf(Ec[tid*68 + d], __ldg(cvb + d), a);
        bC[tid] = a;
    }
    float dM[2][4];
    { // M = attn @ cvw via tf32 MMA, zero cvts
        int n0 = warpN * 16;
#pragma unroll
        for (int nt = 0; nt < 2; nt++)
#pragma unroll
            for (int j = 0; j < 4; j++) dM[nt][j] = 0.f;
#pragma unroll
        for (int k0 = 0; k0 < 64; k0 += 8) {
            unsigned a0 = fbits(Ec[(m0+g)*68   + k0 + cl]);
            unsigned a1 = fbits(Ec[(m0+g+8)*68 + k0 + cl]);
            unsigned a2 = fbits(Ec[(m0+g)*68   + k0 + cl + 4]);
            unsigned a3 = fbits(Ec[(m0+g+8)*68 + k0 + cl + 4]);
#pragma unroll
            for (int nt = 0; nt < 2; nt++) {
                unsigned b0 = fbits(__ldg(g_cvwt + (size_t)(k0+cl)*64   + n0 + nt*8 + g));
                unsigned b1 = fbits(__ldg(g_cvwt + (size_t)(k0+cl+4)*64 + n0 + nt*8 + g));
                mma_tf32(dM[nt], a0, a1, a2, a3, b0, b1);
            }
        }
    }
    __syncthreads();
    {   // store M pre-rounded
        int n0 = warpN * 16;
#pragma unroll
        for (int nt = 0; nt < 2; nt++) {
            int e = n0 + nt*8 + 2*cl;
            *reinterpret_cast<float2*>(M + (m0+g)*68 + e)   = make_float2(rnd(dM[nt][0]), rnd(dM[nt][1]));
            *reinterpret_cast<float2*>(M + (m0+g+8)*68 + e) = make_float2(rnd(dM[nt][2]), rnd(dM[nt][3]));
        }
    }
    __syncthreads();

    { // av = M @ ys + bC via tf32 MMA; store av PRE-ROUNDED
        int n0 = warpN * 32;
        float d4[4][4];
        float b0v = bC[m0+g], b1v = bC[m0+g+8];
#pragma unroll
        for (int nt = 0; nt < 4; nt++) {
            d4[nt][0] = b0v; d4[nt][1] = b0v;
            d4[nt][2] = b1v; d4[nt][3] = b1v;
        }
#pragma unroll
        for (int k0 = 0; k0 < 64; k0 += 8) {
            unsigned a0 = fbits(M[(m0+g)*68   + k0 + cl]);
            unsigned a1 = fbits(M[(m0+g+8)*68 + k0 + cl]);
            unsigned a2 = fbits(M[(m0+g)*68   + k0 + cl + 4]);
            unsigned a3 = fbits(M[(m0+g+8)*68 + k0 + cl + 4]);
#pragma unroll
            for (int nt = 0; nt < 4; nt++) {
                unsigned b0 = tf32b(ys[(k0+cl)*SY   + n0 + nt*8 + g]);
                unsigned b1 = tf32b(ys[(k0+cl+4)*SY + n0 + nt*8 + g]);
                mma_tf32(d4[nt], a0, a1, a2, a3, b0, b1);
            }
        }
        float* dst = g_av + (size_t)b*1048576 + (size_t)v*TT;
#pragma unroll
        for (int nt = 0; nt < 4; nt++) {
            int t = n0 + nt*8 + 2*cl;
            *reinterpret_cast<float2*>(dst + (size_t)(m0+g)*16384 + t)   = make_float2(rnd(d4[nt][0]), rnd(d4[nt][1]));
            *reinterpret_cast<float2*>(dst + (size_t)(m0+g+8)*16384 + t) = make_float2(rnd(d4[nt][2]), rnd(d4[nt][3]));
        }
    }
}

// ------------- k_final: tf32 mma 3x3 conv + recombine -------------
#define AVR 20
#define AVC 360          // 18*AVR
#define CSP 260          // convS pitch, multiple of 4
__global__ __launch_bounds__(256, 2) void k_final(
    const float* __restrict__ gamma_p, const float* __restrict__ sigma_p,
    float* __restrict__ out) {
    extern __shared__ float smf[];
    float* avs = smf;                 // [16 ci][18 rows][AVR] (pre-rounded values)
    float* wss = smf + 16*AVC;        // [16 ci][9 kk][64 o]  (pre-rounded)
    float* convS = smf;               // alias after mma: [64 o][CSP]
    float* scS = smf + 64*CSP;        // [2][256] scales
    int b = blockIdx.y, tile = blockIdx.x;
    int v0 = (tile >> 3) * 16, t0 = (tile & 7) * 16;
    int tid = threadIdx.x, lane = tid & 31, warp = tid >> 5;
    int g = lane >> 2, c = lane & 3;
    int warpM = warp >> 1, warpN = warp & 1;

    float d[16][4];
#pragma unroll
    for (int i = 0; i < 16; i++)
#pragma unroll
        for (int j = 0; j < 4; j++) d[i][j] = 0.f;

    for (int chunk = 0; chunk < 4; chunk++) {
        int ci0 = chunk * 16;
        __syncthreads();
        for (int i = tid; i < 16*324; i += 256) {
            int ci = i / 324, rr = i - ci*324;
            int r = rr / 18, cc = rr - r*18;
            int vv = v0 - 1 + r, t = t0 - 1 + cc;
            float val = 0.f;
            if (vv >= 0 && vv < 128 && t >= 0 && t < 128)
                val = g_av[(size_t)(b*64 + ci0 + ci)*16384 + (size_t)vv*128 + t];
            avs[ci*AVC + r*AVR + cc] = val;
        }
        for (int i = tid; i < 16*576; i += 256)
            wss[i] = g_wtr[ci0*576 + i];
        __syncthreads();

        const unsigned* wsu = reinterpret_cast<const unsigned*>(wss);
#pragma unroll
        for (int kk = 0; kk < 9; kk++) {
            int dv = kk / 3, dt = kk - dv*3;
#pragma unroll
            for (int ks = 0; ks < 2; ks++) {
                const unsigned* wp = wsu + (ks*8 + c)*576 + kk*64 + warpM*16 + g;
                unsigned a0 = wp[0], a1 = wp[8];
                unsigned a2 = wp[4*576], a3 = wp[4*576 + 8];
                int cb0 = (ks*8 + c)*AVC + dv*AVR + dt;
#pragma unroll
                for (int nt = 0; nt < 16; nt++) {
                    int pr = warpN*8 + (nt >> 1);
                    int pc = (nt & 1)*8 + g;
                    unsigned f0 = fbits(avs[cb0 + pr*AVR + pc]);
                    unsigned f1 = fbits(avs[cb0 + 4*AVC + pr*AVR + pc]);
                    mma_tf32(d[nt], a0, a1, a2, a3, f0, f1);
                }
            }
        }
    }
    __syncthreads();

#pragma unroll
    for (int nt = 0; nt < 16; nt++) {
        int pr = warpN*8 + (nt >> 1);
        int pc = (nt & 1)*8 + 2*c;
        int pix = pr*16 + pc;
        int o = warpM*16 + g;
        *reinterpret_cast<float2*>(convS + o*CSP + pix)     = make_float2(d[nt][0], d[nt][1]);
        *reinterpret_cast<float2*>(convS + (o+8)*CSP + pix) = make_float2(d[nt][2], d[nt][3]);
    }
    {
        float gamma = __ldg(gamma_p);
        int v = v0 + (tid >> 4), t = t0 + (tid & 15);
        size_t sidx = ((size_t)b*VV + v)*TT + t;
        float mH = __ldg(&g_mH[sidx]), ZH = __ldg(&g_ZH[sidx]);
        float mW = __ldg(&g_mW[sidx]), ZW = __ldg(&g_ZW[sidx]);
        float m = fmaxf(mH, mW);
        float eH = __expf(mH - m), eW = __expf(mW - m);
        float inv = gamma / (ZH*eH + ZW*eW);
        scS[tid]       = eH * inv;
        scS[256 + tid] = eW * inv;
    }
    __syncthreads();

    float sigma = __ldg(sigma_p);
    int o8 = warp * 8;
    int c4p = c * 4;
#pragma unroll
    for (int half = 0; half < 2; half++) {
        int rr = g + half*8;
        int pix = rr*16 + c4p;
        float sH0 = scS[pix],   sH1 = scS[pix+1],   sH2 = scS[pix+2],   sH3 = scS[pix+3];
        float sW0 = scS[256+pix], sW1 = scS[256+pix+1], sW2 = scS[256+pix+2], sW3 = scS[256+pix+3];
        int v = v0 + rr, t = t0 + c4p;
#pragma unroll
        for (int oi = 0; oi < 8; oi++) {
            int o = o8 + oi;
            size_t oidx = (((size_t)b*CO + o)*VV + v)*TT + t;
            float4 cv = ld4s(convS + o*CSP + pix);
            float4 yv = ld4g(&g_y[oidx]);
            float4 oh = ld4g(&g_OH[oidx]);
            float4 ow = ld4g(&g_OW[oidx]);
            float4 r;
            r.x = yv.x + sH0*oh.x + sW0*ow.x + sigma*cv.x;
            r.y = yv.y + sH1*oh.y + sW1*ow.y + sigma*cv.y;
            r.z = yv.z + sH2*oh.z + sW2*ow.z + sigma*cv.z;
            r.w = yv.w + sH3*oh.w + sW3*ow.w + sigma*cv.w;
            *reinterpret_cast<float4*>(out + oidx) = r;
        }
    }
}

// ---------------- launch: stream-parallel DAG ----------------
extern "C" void kernel_launch(void* const* d_in, const int* in_sizes, int n_in,
                              void* d_out, int out_size) {
    (void)in_sizes; (void)n_in; (void)out_size;
    const float* x    = (const float*)d_in[0];
    const float* dc_w = (const float*)d_in[1];
    const float* dc_b = (const float*)d_in[2];
    const float* q_w  = (const float*)d_in[3];
    const float* q_b  = (const float*)d_in[4];
    const float* k_w  = (const float*)d_in[5];
    const float* k_b  = (const float*)d_in[6];
    const float* v_w  = (const float*)d_in[7];
    const float* v_b  = (const float*)d_in[8];
    const float* gamma= (const float*)d_in[9];
    const float* cq_w = (const float*)d_in[10];
    const float* cq_b = (const float*)d_in[11];
    const float* ck_w = (const float*)d_in[12];
    const float* ck_b = (const float*)d_in[13];
    const float* cv_w = (const float*)d_in[14];
    const float* cv_b = (const float*)d_in[15];
    const float* av_w = (const float*)d_in[16];
    const float* sigma= (const float*)d_in[17];
    float* out = (float*)d_out;

    float *py, *pytr, *pOH;
    cudaGetSymbolAddress((void**)&py,   g_y);
    cudaGetSymbolAddress((void**)&pytr, g_ytr);
    cudaGetSymbolAddress((void**)&pOH,  g_OH);

    const int SMEM_ATT = 208*SY*4;                  // 109,824 B
    const int SMEM_C   = (192*SY + 64)*4;           // 101,632 B
    const int SMEM_F   = (64*CSP + 512)*4;          // 68,608 B

    static cudaStream_t s1 = nullptr, s2 = nullptr;
    static cudaEvent_t evy = nullptr, evw = nullptr, evc = nullptr;
    if (!s1) {
        cudaFuncSetAttribute(k_att<false>, cudaFuncAttributeMaxDynamicSharedMemorySize, SMEM_ATT);
        cudaFuncSetAttribute(k_att<true>,  cudaFuncAttributeMaxDynamicSharedMemorySize, SMEM_ATT);
        cudaFuncSetAttribute(k_c,          cudaFuncAttributeMaxDynamicSharedMemorySize, SMEM_C);
        cudaFuncSetAttribute(k_final,      cudaFuncAttributeMaxDynamicSharedMemorySize, SMEM_F);
        cudaStreamCreateWithFlags(&s1, cudaStreamNonBlocking);
        cudaStreamCreateWithFlags(&s2, cudaStreamNonBlocking);
        cudaEventCreateWithFlags(&evy, cudaEventDisableTiming);
        cudaEventCreateWithFlags(&evw, cudaEventDisableTiming);
        cudaEventCreateWithFlags(&evc, cudaEventDisableTiming);
    }

    // independent prologue on s1
    k_wt <<<144, 256, 0, s1>>>(av_w);
    k_wv <<<16, 256, 0, s1>>>(cv_w);

    // default stream: weight transpose, k_y, then fork
    k_wd <<<64, 256>>>(dc_w);
    k_y  <<<dim3(128, 8), 256>>>(x, dc_b);
    cudaEventRecord(evy, 0);
    cudaStreamWaitEvent(s1, evy, 0);
    cudaStreamWaitEvent(s2, evy, 0);

    // s1: W-attention  |  s2: channel attention  |  default: tr -> H-attention -> tr
    k_att<false><<<dim3(128, 8), 512, SMEM_ATT, s1>>>(q_w, q_b, k_w, k_b, v_w, v_b);
    cudaEventRecord(evw, s1);
    k_c  <<<dim3(128, 8), 512, SMEM_C, s2>>>(cq_w, cq_b, ck_w, ck_b, cv_b);
    cudaEventRecord(evc, s2);

    k_tr <<<dim3(16, 64, 8), dim3(32, 8)>>>(py, pytr, 16384, 128, 128, 8192);
    k_att<true> <<<dim3(128, 8), 512, SMEM_ATT>>>(q_w, q_b, k_w, k_b, v_w, v_b);
    k_tr <<<dim3(16, 64, 8), dim3(32, 8)>>>(pytr, pOH, 128, 8192, 16384, 128);

    // join and finish
    cudaStreamWaitEvent(0, evw, 0);
    cudaStreamWaitEvent(0, evc, 0);
    k_final<<<dim3(64, 8), 256, SMEM_F>>>(gamma, sigma, out);
}

// round 16
// speedup vs baseline: 1.2678x; 1.0094x over previous
#include <cuda_runtime.h>
#include <math.h>

#define BB 8
#define CIN 256
#define CO 64
#define VV 128
#define TT 128
#define SY 132

__device__ float g_y  [BB*CO*VV*TT];
__device__ float g_ytr[BB*TT*CO*VV];   // y_tr, later reused as OH_tr
__device__ float g_OH [BB*CO*VV*TT];
__device__ float g_OW [BB*CO*VV*TT];
__device__ float g_av [BB*CO*VV*TT];   // pre-rounded tf32 bits (written by k_c)
__device__ float g_mH [BB*VV*TT];
__device__ float g_ZH [BB*VV*TT];
__device__ float g_mW [BB*VV*TT];
__device__ float g_ZW [BB*VV*TT];
__device__ float g_wtr[64*576];        // [ci][kk][o], tf32-rounded bits
__device__ float g_cvwt[64*64];        // cvw pre-rounded tf32 bits
__device__ float g_dwt[256*64];        // dc_w transposed [ci][o], fp32 exact

typedef unsigned long long u64;

__device__ __forceinline__ float4 ld4s(const float* p){ return *reinterpret_cast<const float4*>(p); }
__device__ __forceinline__ void st4s(float* p, float4 v){ *reinterpret_cast<float4*>(p) = v; }
__device__ __forceinline__ float4 ld4g(const float* p){ return __ldg(reinterpret_cast<const float4*>(p)); }
__device__ __forceinline__ ulonglong2 ld2x2s(const float* p){ return *reinterpret_cast<const ulonglong2*>(p); }
__device__ __forceinline__ void st2x2s(float* p, ulonglong2 v){ *reinterpret_cast<ulonglong2*>(p) = v; }
__device__ __forceinline__ u64 pk2(float x){ u64 r; asm("mov.b64 %0,{%1,%1};" : "=l"(r) : "f"(x)); return r; }
__device__ __forceinline__ float2 up2(u64 a){ float2 f; asm("mov.b64 {%0,%1},%2;" : "=f"(f.x), "=f"(f.y) : "l"(a)); return f; }
__device__ __forceinline__ u64 fma2(u64 a, u64 b, u64 c){
    u64 d; asm("fma.rn.f32x2 %0,%1,%2,%3;" : "=l"(d) : "l"(a), "l"(b), "l"(c)); return d;
}
__device__ __forceinline__ float dot4(float4 a, float4 b, float c){
    c = fmaf(a.x,b.x,c); c = fmaf(a.y,b.y,c); c = fmaf(a.z,b.z,c); return fmaf(a.w,b.w,c);
}
__device__ __forceinline__ unsigned tf32b(float x){
    unsigned u; asm("cvt.rna.tf32.f32 %0, %1;" : "=r"(u) : "f"(x)); return u;
}
__device__ __forceinline__ float rnd(float x){ return __uint_as_float(tf32b(x)); }
__device__ __forceinline__ unsigned fbits(float x){ return __float_as_uint(x); }
__device__ __forceinline__ void mma_tf32(float* d, unsigned a0, unsigned a1, unsigned a2, unsigned a3,
                                         unsigned b0, unsigned b1){
    asm("mma.sync.aligned.m16n8k8.row.col.f32.tf32.tf32.f32 "
        "{%0,%1,%2,%3}, {%4,%5,%6,%7}, {%8,%9}, {%0,%1,%2,%3};"
        : "+f"(d[0]), "+f"(d[1]), "+f"(d[2]), "+f"(d[3])
        : "r"(a0), "r"(a1), "r"(a2), "r"(a3), "r"(b0), "r"(b1));
}

// ---------------- prep: transpose dc_w -> g_dwt[ci][o] ----------------
__global__ __launch_bounds__(256) void k_wd(const float* __restrict__ w) {
    int i = blockIdx.x*256 + threadIdx.x;   // < 16384
    int ci = i >> 6, o = i & 63;
    g_dwt[i] = __ldg(w + (size_t)o*CIN + ci);
}

// ---------------- k_y: y = dc_w @ xp + dc_b ----------------
// acc layout: [t][o-pair]; x is the broadcast scalar (4 pk2/ci), weights load as u64 pairs.
__global__ __launch_bounds__(256) void k_y(const float* __restrict__ x,
                                           const float* __restrict__ bias) {
    __shared__ float xs[32][128];
    __shared__ float wsT[32*64];   // [ci][o]
    int v = blockIdx.x, b = blockIdx.y;
    int tid = threadIdx.x, lane = tid & 31, warp = tid >> 5, t4 = lane*4;
    int o8 = warp * 8;
    ulonglong2 acc[4][2];
#pragma unroll
    for (int j = 0; j < 4; j++)
#pragma unroll
        for (int p = 0; p < 2; p++) { acc[j][p].x = 0ull; acc[j][p].y = 0ull; }
    bool vin = (v >= 1 && v <= 126);
    for (int c0 = 0; c0 < CIN; c0 += 32) {
        for (int i = tid; i < 32*128; i += 256) {
            int ci = i >> 7, t = i & 127;
            float val = 0.f;
            if (vin && t >= 1 && t <= 126)
                val = x[(((size_t)b*CIN + c0 + ci)*126 + (v-1))*126 + (t-1)];
            xs[ci][t] = val;
        }
        for (int i = tid; i < 512; i += 256)
            st4s(wsT + i*4, ld4g(g_dwt + c0*64 + i*4));
        __syncthreads();
#pragma unroll 4
        for (int ci = 0; ci < 32; ci++) {
            float4 xv = ld4s(&xs[ci][t4]);
            u64 xp[4] = {pk2(xv.x), pk2(xv.y), pk2(xv.z), pk2(xv.w)};
            ulonglong2 wA = ld2x2s(wsT + ci*64 + o8);       // (o8,o8+1),(o8+2,o8+3)
            ulonglong2 wB = ld2x2s(wsT + ci*64 + o8 + 4);   // (o8+4..o8+7)
#pragma unroll
            for (int j = 0; j < 4; j++) {
                acc[j][0].x = fma2(xp[j], wA.x, acc[j][0].x);
                acc[j][0].y = fma2(xp[j], wA.y, acc[j][0].y);
                acc[j][1].x = fma2(xp[j], wB.x, acc[j][1].x);
                acc[j][1].y = fma2(xp[j], wB.y, acc[j][1].y);
            }
        }
        __syncthreads();
    }
    // epilogue: regroup to per-o float4 over t, add bias, coalesced store
    float vals[4][8];
#pragma unroll
    for (int j = 0; j < 4; j++) {
        float2 a0 = up2(acc[j][0].x), a1 = up2(acc[j][0].y);
        float2 a2 = up2(acc[j][1].x), a3 = up2(acc[j][1].y);
        vals[j][0] = a0.x; vals[j][1] = a0.y; vals[j][2] = a1.x; vals[j][3] = a1.y;
        vals[j][4] = a2.x; vals[j][5] = a2.y; vals[j][6] = a3.x; vals[j][7] = a3.y;
    }
#pragma unroll
    for (int k = 0; k < 8; k++) {
        int o = o8 + k;
        float bo = __ldg(bias + o);
        st4s(&g_y[(((size_t)b*CO + o)*VV + v)*TT + t4],
             make_float4(vals[0][k]+bo, vals[1][k]+bo, vals[2][k]+bo, vals[3][k]+bo));
    }
}

// ------------- generic 128x128 transpose per (b,c) -------------
__global__ __launch_bounds__(256) void k_tr(const float* __restrict__ src,
                                            float* __restrict__ dst,
                                            int sc, int sr, int dc, int dq) {
    __shared__ float s[32][33];
    int tile = blockIdx.x, c = blockIdx.y, b = blockIdx.z;
    int r0 = (tile >> 2) * 32, q0 = (tile & 3) * 32;
    int tx = threadIdx.x, ty = threadIdx.y;
    const float* sp = src + (size_t)b*1048576 + (size_t)c*sc;
#pragma unroll
    for (int i = 0; i < 32; i += 8) s[ty+i][tx] = sp[(size_t)(r0+ty+i)*sr + q0 + tx];
    __syncthreads();
    float* dp = dst + (size_t)b*1048576 + (size_t)c*dc;
#pragma unroll
    for (int i = 0; i < 32; i += 8) dp[(size_t)(q0+ty+i)*dq + r0 + tx] = s[tx][ty+i];
}

// ---------------- weight transposes (tf32 pre-rounded) ----------------
__global__ __launch_bounds__(256) void k_wt(const float* __restrict__ avw) {
    int i = blockIdx.x*256 + threadIdx.x;   // < 36864
    int ci = i / 576, rem = i - ci*576;
    int kk = rem >> 6, o = rem & 63;
    g_wtr[i] = rnd(__ldg(avw + (size_t)o*576 + ci*9 + kk));
}
__global__ __launch_bounds__(256) void k_wv(const float* __restrict__ cvw) {
    int i = blockIdx.x*256 + threadIdx.x;   // < 4096
    g_cvwt[i] = rnd(__ldg(cvw + i));
}

// ------------- spatial attention (W / H) -------------
template<bool ISH>
__global__ __launch_bounds__(512, 2) void k_att(
    const float* __restrict__ qw, const float* __restrict__ qb,
    const float* __restrict__ kw, const float* __restrict__ kb,
    const float* __restrict__ vw, const float* __restrict__ vb) {
    int idx = blockIdx.x, b = blockIdx.y;
    int tid = threadIdx.x, lane = tid & 31, warp = tid >> 5, t4 = lane*4;
    extern __shared__ float sm[];
    float* E  = sm;              // E_T[s][t]
    float* ys = sm;              // alias rows 0..63
    float* qs = sm + 128*SY;
    float* ks = qs + 8*SY;
    float* vs = ks + 8*SY;       // stored tf32-pre-rounded
    float* pm = qs;
    float* pz = qs + 512;

    if (ISH) {
        const float* ysrc = g_ytr + (size_t)(b*TT + idx)*8192;
        for (int i = tid*4; i < 8192; i += 2048)
            st4s(ys + (i>>7)*SY + (i&127), ld4g(ysrc + i));
    } else {
        const float* ysrc = g_y + (size_t)b*1048576 + (size_t)idx*TT;
        for (int i = tid; i < 2048; i += 512) {
            int c = i >> 5, tt = (i & 31)*4;
            st4s(ys + c*SY + tt, ld4g(ysrc + (size_t)c*16384 + tt));
        }
    }
    __syncthreads();

    { // FUSED q/k/v projection: one pass over ys
        int c4 = warp * 4;
        int which = warp >> 3, cq = warp & 7;
        const float* Wqk = which ? kw : qw;
        ulonglong2 acc[4], qa;
#pragma unroll
        for (int i = 0; i < 4; i++) { u64 bp = pk2(__ldg(vb + c4 + i)); acc[i].x = bp; acc[i].y = bp; }
        { u64 bp = pk2(__ldg((which ? kb : qb) + cq)); qa.x = bp; qa.y = bp; }
#pragma unroll 2
        for (int cc = 0; cc < 64; cc += 4) {
            ulonglong2 y0 = ld2x2s(ys + (cc+0)*SY + t4);
            ulonglong2 y1 = ld2x2s(ys + (cc+1)*SY + t4);
            ulonglong2 y2 = ld2x2s(ys + (cc+2)*SY + t4);
            ulonglong2 y3 = ld2x2s(ys + (cc+3)*SY + t4);
            float4 wq = ld4g(Wqk + (size_t)cq*64 + cc);
            qa.x = fma2(pk2(wq.x), y0.x, qa.x); qa.y = fma2(pk2(wq.x), y0.y, qa.y);
            qa.x = fma2(pk2(wq.y), y1.x, qa.x); qa.y = fma2(pk2(wq.y), y1.y, qa.y);
            qa.x = fma2(pk2(wq.z), y2.x, qa.x); qa.y = fma2(pk2(wq.z), y2.y, qa.y);
            qa.x = fma2(pk2(wq.w), y3.x, qa.x); qa.y = fma2(pk2(wq.w), y3.y, qa.y);
#pragma unroll
            for (int i = 0; i < 4; i++) {
                float4 wv = ld4g(vw + (size_t)(c4+i)*64 + cc);
                acc[i].x = fma2(pk2(wv.x), y0.x, acc[i].x); acc[i].y = fma2(pk2(wv.x), y0.y, acc[i].y);
                acc[i].x = fma2(pk2(wv.y), y1.x, acc[i].x); acc[i].y = fma2(pk2(wv.y), y1.y, acc[i].y);
                acc[i].x = fma2(pk2(wv.z), y2.x, acc[i].x); acc[i].y = fma2(pk2(wv.z), y2.y, acc[i].y);
                acc[i].x = fma2(pk2(wv.w), y3.x, acc[i].x); acc[i].y = fma2(pk2(wv.w), y3.y, acc[i].y);
            }
        }
#pragma unroll
        for (int i = 0; i < 4; i++) {   // store vs pre-rounded to tf32 bits
            float2 lo = up2(acc[i].x), hi = up2(acc[i].y);
            st4s(vs + (c4+i)*SY + t4,
                 make_float4(rnd(lo.x), rnd(lo.y), rnd(hi.x), rnd(hi.y)));
        }
        st2x2s((which ? ks : qs) + cq*SY + t4, qa);   // q/k stay fp32-exact
    }
    __syncthreads();

    { // QK (f32x2) -> E_T[s][t]
        int s0 = (tid >> 4) * 4, t0 = (tid & 15) * 8;
        u64 acc[4][4];
#pragma unroll
        for (int i = 0; i < 4; i++)
#pragma unroll
            for (int j = 0; j < 4; j++) acc[i][j] = 0ull;
#pragma unroll
        for (int c = 0; c < 8; c++) {
            float kv[4];
#pragma unroll
            for (int i = 0; i < 4; i++) kv[i] = ks[c*SY + s0 + i];
            ulonglong2 qA = ld2x2s(qs + c*SY + t0);
            ulonglong2 qB = ld2x2s(qs + c*SY + t0 + 4);
#pragma unroll
            for (int i = 0; i < 4; i++) {
                u64 kp = pk2(kv[i]);
                acc[i][0] = fma2(kp, qA.x, acc[i][0]);
                acc[i][1] = fma2(kp, qA.y, acc[i][1]);
                acc[i][2] = fma2(kp, qB.x, acc[i][2]);
                acc[i][3] = fma2(kp, qB.y, acc[i][3]);
            }
        }
#pragma unroll
        for (int i = 0; i < 4; i++) {
            float2 p0 = up2(acc[i][0]), p1 = up2(acc[i][1]);
            float2 p2 = up2(acc[i][2]), p3 = up2(acc[i][3]);
            float vals[8] = {p0.x,p0.y,p1.x,p1.y,p2.x,p2.y,p3.x,p3.y};
            if (ISH) {
                int d = s0 + i - t0;
                if (d >= 0 && d < 8) vals[d] = -1e30f;
            }
            st4s(E + (s0+i)*SY + t0,   make_float4(vals[0],vals[1],vals[2],vals[3]));
            st4s(E + (s0+i)*SY + t0+4, make_float4(vals[4],vals[5],vals[6],vals[7]));
        }
    }
    __syncthreads();

    { // softmax over s per column t; stores PRE-ROUNDED p, Z from rounded p
        int t = tid & 127, q = tid >> 7;
        int sbeg = q * 32;
        float m = -INFINITY;
#pragma unroll 8
        for (int s = sbeg; s < sbeg + 32; s++) m = fmaxf(m, E[s*SY + t]);
        pm[q*128 + t] = m;
        __syncthreads();
        float M = fmaxf(fmaxf(pm[t], pm[128+t]), fmaxf(pm[256+t], pm[384+t]));
        float Z = 0.f;
#pragma unroll 8
        for (int s = sbeg; s < sbeg + 32; s++) {
            float p = rnd(__expf(E[s*SY + t] - M));
            E[s*SY + t] = p; Z += p;
        }
        pz[q*128 + t] = Z;
        __syncthreads();
        if (q == 0) {
            float Zt = pz[t] + pz[128+t] + pz[256+t] + pz[384+t];
            if (ISH) { g_mH[((size_t)b*VV + t)*TT + idx] = M; g_ZH[((size_t)b*VV + t)*TT + idx] = Zt; }
            else     { g_mW[((size_t)b*VV + idx)*TT + t] = M; g_ZW[((size_t)b*VV + idx)*TT + t] = Zt; }
        }
    }
    __syncthreads();

    { // apply via tf32 MMA, zero cvts (operands pre-rounded)
        int warpM = warp & 3, warpN = warp >> 2;
        int m0 = warpM * 16, n0 = warpN * 32;
        int g = lane >> 2, c = lane & 3;
        float d[4][4];
#pragma unroll
        for (int nt = 0; nt < 4; nt++)
#pragma unroll
            for (int j = 0; j < 4; j++) d[nt][j] = 0.f;
#pragma unroll 4
        for (int k0 = 0; k0 < 128; k0 += 8) {
            unsigned a0 = fbits(vs[(m0+g)*SY   + k0 + c]);
            unsigned a1 = fbits(vs[(m0+g+8)*SY + k0 + c]);
            unsigned a2 = fbits(vs[(m0+g)*SY   + k0 + c + 4]);
            unsigned a3 = fbits(vs[(m0+g+8)*SY + k0 + c + 4]);
#pragma unroll
            for (int nt = 0; nt < 4; nt++) {
                unsigned b0 = fbits(E[(k0+c)*SY   + n0 + nt*8 + g]);
                unsigned b1 = fbits(E[(k0+c+4)*SY + n0 + nt*8 + g]);
                mma_tf32(d[nt], a0, a1, a2, a3, b0, b1);
            }
        }
        if (ISH) {
            float* dst = g_ytr + (size_t)(b*TT + idx)*8192;
#pragma unroll
            for (int nt = 0; nt < 4; nt++) {
                int t = n0 + nt*8 + 2*c;
                *reinterpret_cast<float2*>(dst + (m0+g)*128 + t)   = make_float2(d[nt][0], d[nt][1]);
                *reinterpret_cast<float2*>(dst + (m0+g+8)*128 + t) = make_float2(d[nt][2], d[nt][3]);
            }
        } else {
            float* dst = g_OW + (size_t)b*1048576 + (size_t)idx*TT;
#pragma unroll
            for (int nt = 0; nt < 4; nt++) {
                int t = n0 + nt*8 + 2*c;
                *reinterpret_cast<float2*>(dst + (size_t)(m0+g)*16384 + t)   = make_float2(d[nt][0], d[nt][1]);
                *reinterpret_cast<float2*>(dst + (size_t)(m0+g+8)*16384 + t) = make_float2(d[nt][2], d[nt][3]);
            }
        }
    }
}

// ------------- channel attention per (b,v) -------------
__global__ __launch_bounds__(512, 2) void k_c(
    const float* __restrict__ cqw, const float* __restrict__ cqb,
    const float* __restrict__ ckw, const float* __restrict__ ckb,
    const float* __restrict__ cvb) {
    int v = blockIdx.x, b = blockIdx.y;
    int tid = threadIdx.x, lane = tid & 31, warp = tid >> 5, t4 = lane*4;
    extern __shared__ float sm[];
    float* ys = sm;
    float* qc = sm + 64*SY;
    float* kc = sm + 128*SY;
    float* bC = sm + 192*SY;
    float* Ec = kc;              // alias (pitch 68)
    float* M  = qc;              // alias (pitch 68)
    int c4 = warp * 4;
    int g = lane >> 2, cl = lane & 3;
    int warpM = warp & 3, warpN = warp >> 2;
    int m0 = warpM * 16;

    const float* ysrc = g_y + (size_t)b*1048576 + (size_t)v*TT;
    for (int i = tid; i < 2048; i += 512) {
        int c = i >> 5, tt = (i & 31)*4;
        st4s(ys + c*SY + tt, ld4g(ysrc + (size_t)c*16384 + tt));
    }
    __syncthreads();

    { // FUSED qc+kc projection (fp32-exact)
        ulonglong2 qa[4], ka[4];
#pragma unroll
        for (int i = 0; i < 4; i++) {
            u64 bq = pk2(__ldg(cqb + c4 + i)); qa[i].x = bq; qa[i].y = bq;
            u64 bk = pk2(__ldg(ckb + c4 + i)); ka[i].x = bk; ka[i].y = bk;
        }
#pragma unroll 2
        for (int cc = 0; cc < 64; cc += 2) {
            ulonglong2 y0 = ld2x2s(ys + (cc+0)*SY + t4);
            ulonglong2 y1 = ld2x2s(ys + (cc+1)*SY + t4);
#pragma unroll
            for (int i = 0; i < 4; i++) {
                float2 wq = __ldg(reinterpret_cast<const float2*>(cqw + (size_t)(c4+i)*64 + cc));
                float2 wk = __ldg(reinterpret_cast<const float2*>(ckw + (size_t)(c4+i)*64 + cc));
                qa[i].x = fma2(pk2(wq.x), y0.x, qa[i].x); qa[i].y = fma2(pk2(wq.x), y0.y, qa[i].y);
                qa[i].x = fma2(pk2(wq.y), y1.x, qa[i].x); qa[i].y = fma2(pk2(wq.y), y1.y, qa[i].y);
                ka[i].x = fma2(pk2(wk.x), y0.x, ka[i].x); ka[i].y = fma2(pk2(wk.x), y0.y, ka[i].y);
                ka[i].x = fma2(pk2(wk.y), y1.x, ka[i].x); ka[i].y = fma2(pk2(wk.y), y1.y, ka[i].y);
            }
        }
#pragma unroll
        for (int i = 0; i < 4; i++) {
            st2x2s(qc + (c4+i)*SY + t4, qa[i]);
            st2x2s(kc + (c4+i)*SY + t4, ka[i]);
        }
    }
    __syncthreads();

    { // Ec = qc*kc^T via 3xtf32 MMA (fp32-accurate energies)
        int n0 = warpN * 16;
        float d2[2][4];
#pragma unroll
        for (int nt = 0; nt < 2; nt++)
#pragma unroll
            for (int j = 0; j < 4; j++) d2[nt][j] = 0.f;
#pragma unroll 2
        for (int k0 = 0; k0 < 128; k0 += 8) {
            float af0 = qc[(m0+g)*SY   + k0 + cl];
            float af1 = qc[(m0+g+8)*SY + k0 + cl];
            float af2 = qc[(m0+g)*SY   + k0 + cl + 4];
            float af3 = qc[(m0+g+8)*SY + k0 + cl + 4];
            unsigned ah0 = tf32b(af0), ah1 = tf32b(af1), ah2 = tf32b(af2), ah3 = tf32b(af3);
            unsigned al0 = tf32b(af0 - __uint_as_float(ah0));
            unsigned al1 = tf32b(af1 - __uint_as_float(ah1));
            unsigned al2 = tf32b(af2 - __uint_as_float(ah2));
            unsigned al3 = tf32b(af3 - __uint_as_float(ah3));
#pragma unroll
            for (int nt = 0; nt < 2; nt++) {
                float bf0 = kc[(n0 + nt*8 + g)*SY + k0 + cl];
                float bf1 = kc[(n0 + nt*8 + g)*SY + k0 + cl + 4];
                unsigned bh0 = tf32b(bf0), bh1 = tf32b(bf1);
                unsigned bl0 = tf32b(bf0 - __uint_as_float(bh0));
                unsigned bl1 = tf32b(bf1 - __uint_as_float(bh1));
                mma_tf32(d2[nt], ah0, ah1, ah2, ah3, bh0, bh1);
                mma_tf32(d2[nt], ah0, ah1, ah2, ah3, bl0, bl1);
                mma_tf32(d2[nt], al0, al1, al2, al3, bh0, bh1);
            }
        }
        __syncthreads();
#pragma unroll
        for (int nt = 0; nt < 2; nt++) {
            int dd = n0 + nt*8 + 2*cl;
            *reinterpret_cast<float2*>(Ec + (m0+g)*68 + dd)   = make_float2(d2[nt][0], d2[nt][1]);
            *reinterpret_cast<float2*>(Ec + (m0+g+8)*68 + dd) = make_float2(d2[nt][2], d2[nt][3]);
        }
    }
    __syncthreads();

    { // softmax rows of Ec (8 threads/row); store pre-rounded weights
        int r = tid >> 3, sub = tid & 7;
        float* row = Ec + r*68;
        float4 x0 = ld4s(row + sub*4), x1 = ld4s(row + sub*4 + 32);
        float m = fmaxf(fmaxf(fmaxf(x0.x,x0.y),fmaxf(x0.z,x0.w)),
                        fmaxf(fmaxf(x1.x,x1.y),fmaxf(x1.z,x1.w)));
        m = fmaxf(m, __shfl_xor_sync(~0u, m, 1));
        m = fmaxf(m, __shfl_xor_sync(~0u, m, 2));
        m = fmaxf(m, __shfl_xor_sync(~0u, m, 4));
        x0.x=__expf(x0.x-m); x0.y=__expf(x0.y-m); x0.z=__expf(x0.z-m); x0.w=__expf(x0.w-m);
        x1.x=__expf(x1.x-m); x1.y=__expf(x1.y-m); x1.z=__expf(x1.z-m); x1.w=__expf(x1.w-m);
        float Z = x0.x+x0.y+x0.z+x0.w + x1.x+x1.y+x1.z+x1.w;
        Z += __shfl_xor_sync(~0u, Z, 1);
        Z += __shfl_xor_sync(~0u, Z, 2);
        Z += __shfl_xor_sync(~0u, Z, 4);
        float inv = 1.f / Z;
        x0.x = rnd(x0.x*inv); x0.y = rnd(x0.y*inv); x0.z = rnd(x0.z*inv); x0.w = rnd(x0.w*inv);
        x1.x = rnd(x1.x*inv); x1.y = rnd(x1.y*inv); x1.z = rnd(x1.z*inv); x1.w = rnd(x1.w*inv);
        st4s(row + sub*4, x0); st4s(row + sub*4 + 32, x1);
    }
    __syncthreads();

    if (tid < 64) {   // bC = attn @ cvb
        float a = 0.f;
        for (int d = 0; d < 64; d++) a = fmaf(Ec[tid*68 + d], __ldg(cvb + d), a);
        bC[tid] = a;
    }
    float dM[2][4];
    { // M = attn @ cvw via tf32 MMA, zero cvts
        int n0 = warpN * 16;
#pragma unroll
        for (int nt = 0; nt < 2; nt++)
#pragma unroll
            for (int j = 0; j < 4; j++) dM[nt][j] = 0.f;
#pragma unroll
        for (int k0 = 0; k0 < 64; k0 += 8) {
            unsigned a0 = fbits(Ec[(m0+g)*68   + k0 + cl]);
            unsigned a1 = fbits(Ec[(m0+g+8)*68 + k0 + cl]);
            unsigned a2 = fbits(Ec[(m0+g)*68   + k0 + cl + 4]);
            unsigned a3 = fbits(Ec[(m0+g+8)*68 + k0 + cl + 4]);
#pragma unroll
            for (int nt = 0; nt < 2; nt++) {
                unsigned b0 = fbits(__ldg(g_cvwt + (size_t)(k0+cl)*64   + n0 + nt*8 + g));
                unsigned b1 = fbits(__ldg(g_cvwt + (size_t)(k0+cl+4)*64 + n0 + nt*8 + g));
                mma_tf32(dM[nt], a0, a1, a2, a3, b0, b1);
            }
        }
    }
    __syncthreads();
    {   // store M pre-rounded
        int n0 = warpN * 16;
#pragma unroll
        for (int nt = 0; nt < 2; nt++) {
            int e = n0 + nt*8 + 2*cl;
            *reinterpret_cast<float2*>(M + (m0+g)*68 + e)   = make_float2(rnd(dM[nt][0]), rnd(dM[nt][1]));
            *reinterpret_cast<float2*>(M + (m0+g+8)*68 + e) = make_float2(rnd(dM[nt][2]), rnd(dM[nt][3]));
        }
    }
    __syncthreads();

    { // av = M @ ys + bC via tf32 MMA; store av PRE-ROUNDED
        int n0 = warpN * 32;
        float d4[4][4];
        float b0v = bC[m0+g], b1v = bC[m0+g+8];
#pragma unroll
        for (int nt = 0; nt < 4; nt++) {
            d4[nt][0] = b0v; d4[nt][1] = b0v;
            d4[nt][2] = b1v; d4[nt][3] = b1v;
        }
#pragma unroll
        for (int k0 = 0; k0 < 64; k0 += 8) {
            unsigned a0 = fbits(M[(m0+g)*68   + k0 + cl]);
            unsigned a1 = fbits(M[(m0+g+8)*68 + k0 + cl]);
            unsigned a2 = fbits(M[(m0+g)*68   + k0 + cl + 4]);
            unsigned a3 = fbits(M[(m0+g+8)*68 + k0 + cl + 4]);
#pragma unroll
            for (int nt = 0; nt < 4; nt++) {
                unsigned b0 = tf32b(ys[(k0+cl)*SY   + n0 + nt*8 + g]);
                unsigned b1 = tf32b(ys[(k0+cl+4)*SY + n0 + nt*8 + g]);
                mma_tf32(d4[nt], a0, a1, a2, a3, b0, b1);
            }
        }
        float* dst = g_av + (size_t)b*1048576 + (size_t)v*TT;
#pragma unroll
        for (int nt = 0; nt < 4; nt++) {
            int t = n0 + nt*8 + 2*cl;
            *reinterpret_cast<float2*>(dst + (size_t)(m0+g)*16384 + t)   = make_float2(rnd(d4[nt][0]), rnd(d4[nt][1]));
            *reinterpret_cast<float2*>(dst + (size_t)(m0+g+8)*16384 + t) = make_float2(rnd(d4[nt][2]), rnd(d4[nt][3]));
        }
    }
}

// ------------- k_final: tf32 mma 3x3 conv + recombine -------------
#define AVR 20
#define AVC 360          // 18*AVR
#define CSP 260          // convS pitch, multiple of 4
__global__ __launch_bounds__(256, 2) void k_final(
    const float* __restrict__ gamma_p, const float* __restrict__ sigma_p,
    float* __restrict__ out) {
    extern __shared__ float smf[];
    float* avs = smf;                 // [16 ci][18 rows][AVR] (pre-rounded values)
    float* wss = smf + 16*AVC;        // [16 ci][9 kk][64 o]  (pre-rounded)
    float* convS = smf;               // alias after mma: [64 o][CSP]
    float* scS = smf + 64*CSP;        // [2][256] scales
    int b = blockIdx.y, tile = blockIdx.x;
    int v0 = (tile >> 3) * 16, t0 = (tile & 7) * 16;
    int tid = threadIdx.x, lane = tid & 31, warp = tid >> 5;
    int g = lane >> 2, c = lane & 3;
    int warpM = warp >> 1, warpN = warp & 1;

    float d[16][4];
#pragma unroll
    for (int i = 0; i < 16; i++)
#pragma unroll
        for (int j = 0; j < 4; j++) d[i][j] = 0.f;

    for (int chunk = 0; chunk < 4; chunk++) {
        int ci0 = chunk * 16;
        __syncthreads();
        for (int i = tid; i < 16*324; i += 256) {
            int ci = i / 324, rr = i - ci*324;
            int r = rr / 18, cc = rr - r*18;
            int vv = v0 - 1 + r, t = t0 - 1 + cc;
            float val = 0.f;
            if (vv >= 0 && vv < 128 && t >= 0 && t < 128)
                val = g_av[(size_t)(b*64 + ci0 + ci)*16384 + (size_t)vv*128 + t];
            avs[ci*AVC + r*AVR + cc] = val;
        }
        for (int i = tid; i < 16*576; i += 256)
            wss[i] = g_wtr[ci0*576 + i];
        __syncthreads();

        const unsigned* wsu = reinterpret_cast<const unsigned*>(wss);
#pragma unroll
        for (int kk = 0; kk < 9; kk++) {
            int dv = kk / 3, dt = kk - dv*3;
#pragma unroll
            for (int ks = 0; ks < 2; ks++) {
                const unsigned* wp = wsu + (ks*8 + c)*576 + kk*64 + warpM*16 + g;
                unsigned a0 = wp[0], a1 = wp[8];
                unsigned a2 = wp[4*576], a3 = wp[4*576 + 8];
                int cb0 = (ks*8 + c)*AVC + dv*AVR + dt;
#pragma unroll
                for (int nt = 0; nt < 16; nt++) {
                    int pr = warpN*8 + (nt >> 1);
                    int pc = (nt & 1)*8 + g;
                    unsigned f0 = fbits(avs[cb0 + pr*AVR + pc]);
                    unsigned f1 = fbits(avs[cb0 + 4*AVC + pr*AVR + pc]);
                    mma_tf32(d[nt], a0, a1, a2, a3, f0, f1);
                }
            }
        }
    }
    __syncthreads();

#pragma unroll
    for (int nt = 0; nt < 16; nt++) {
        int pr = warpN*8 + (nt >> 1);
        int pc = (nt & 1)*8 + 2*c;
        int pix = pr*16 + pc;
        int o = warpM*16 + g;
        *reinterpret_cast<float2*>(convS + o*CSP + pix)     = make_float2(d[nt][0], d[nt][1]);
        *reinterpret_cast<float2*>(convS + (o+8)*CSP + pix) = make_float2(d[nt][2], d[nt][3]);
    }
    {
        float gamma = __ldg(gamma_p);
        int v = v0 + (tid >> 4), t = t0 + (tid & 15);
        size_t sidx = ((size_t)b*VV + v)*TT + t;
        float mH = __ldg(&g_mH[sidx]), ZH = __ldg(&g_ZH[sidx]);
        float mW = __ldg(&g_mW[sidx]), ZW = __ldg(&g_ZW[sidx]);
        float m = fmaxf(mH, mW);
        float eH = __expf(mH - m), eW = __expf(mW - m);
        float inv = gamma / (ZH*eH + ZW*eW);
        scS[tid]       = eH * inv;
        scS[256 + tid] = eW * inv;
    }
    __syncthreads();

    float sigma = __ldg(sigma_p);
    int o8 = warp * 8;
    int c4p = c * 4;
#pragma unroll
    for (int half = 0; half < 2; half++) {
        int rr = g + half*8;
        int pix = rr*16 + c4p;
        float sH0 = scS[pix],   sH1 = scS[pix+1],   sH2 = scS[pix+2],   sH3 = scS[pix+3];
        float sW0 = scS[256+pix], sW1 = scS[256+pix+1], sW2 = scS[256+pix+2], sW3 = scS[256+pix+3];
        int v = v0 + rr, t = t0 + c4p;
#pragma unroll
        for (int oi = 0; oi < 8; oi++) {
            int o = o8 + oi;
            size_t oidx = (((size_t)b*CO + o)*VV + v)*TT + t;
            float4 cv = ld4s(convS + o*CSP + pix);
            float4 yv = ld4g(&g_y[oidx]);
            float4 oh = ld4g(&g_OH[oidx]);
            float4 ow = ld4g(&g_OW[oidx]);
            float4 r;
            r.x = yv.x + sH0*oh.x + sW0*ow.x + sigma*cv.x;
            r.y = yv.y + sH1*oh.y + sW1*ow.y + sigma*cv.y;
            r.z = yv.z + sH2*oh.z + sW2*ow.z + sigma*cv.z;
            r.w = yv.w + sH3*oh.w + sW3*ow.w + sigma*cv.w;
            *reinterpret_cast<float4*>(out + oidx) = r;
        }
    }
}

// ---------------- launch: stream-parallel DAG ----------------
extern "C" void kernel_launch(void* const* d_in, const int* in_sizes, int n_in,
                              void* d_out, int out_size) {
    (void)in_sizes; (void)n_in; (void)out_size;
    const float* x    = (const float*)d_in[0];
    const float* dc_w = (const float*)d_in[1];
    const float* dc_b = (const float*)d_in[2];
    const float* q_w  = (const float*)d_in[3];
    const float* q_b  = (const float*)d_in[4];
    const float* k_w  = (const float*)d_in[5];
    const float* k_b  = (const float*)d_in[6];
    const float* v_w  = (const float*)d_in[7];
    const float* v_b  = (const float*)d_in[8];
    const float* gamma= (const float*)d_in[9];
    const float* cq_w = (const float*)d_in[10];
    const float* cq_b = (const float*)d_in[11];
    const float* ck_w = (const float*)d_in[12];
    const float* ck_b = (const float*)d_in[13];
    const float* cv_w = (const float*)d_in[14];
    const float* cv_b = (const float*)d_in[15];
    const float* av_w = (const float*)d_in[16];
    const float* sigma= (const float*)d_in[17];
    float* out = (float*)d_out;

    float *py, *pytr, *pOH;
    cudaGetSymbolAddress((void**)&py,   g_y);
    cudaGetSymbolAddress((void**)&pytr, g_ytr);
    cudaGetSymbolAddress((void**)&pOH,  g_OH);

    const int SMEM_ATT = 208*SY*4;                  // 109,824 B
    const int SMEM_C   = (192*SY + 64)*4;           // 101,632 B
    const int SMEM_F   = (64*CSP + 512)*4;          // 68,608 B

    static cudaStream_t s1 = nullptr, s2 = nullptr;
    static cudaEvent_t evy = nullptr, evw = nullptr, evc = nullptr;
    if (!s1) {
        cudaFuncSetAttribute(k_att<false>, cudaFuncAttributeMaxDynamicSharedMemorySize, SMEM_ATT);
        cudaFuncSetAttribute(k_att<true>,  cudaFuncAttributeMaxDynamicSharedMemorySize, SMEM_ATT);
        cudaFuncSetAttribute(k_c,          cudaFuncAttributeMaxDynamicSharedMemorySize, SMEM_C);
        cudaFuncSetAttribute(k_final,      cudaFuncAttributeMaxDynamicSharedMemorySize, SMEM_F);
        cudaStreamCreateWithFlags(&s1, cudaStreamNonBlocking);
        cudaStreamCreateWithFlags(&s2, cudaStreamNonBlocking);
        cudaEventCreateWithFlags(&evy, cudaEventDisableTiming);
        cudaEventCreateWithFlags(&evw, cudaEventDisableTiming);
        cudaEventCreateWithFlags(&evc, cudaEventDisableTiming);
    }

    // independent prologue on s1
    k_wt <<<144, 256, 0, s1>>>(av_w);
    k_wv <<<16, 256, 0, s1>>>(cv_w);

    // default stream: weight transpose, k_y, then fork
    k_wd <<<64, 256>>>(dc_w);
    k_y  <<<dim3(128, 8), 256>>>(x, dc_b);
    cudaEventRecord(evy, 0);
    cudaStreamWaitEvent(s1, evy, 0);
    cudaStreamWaitEvent(s2, evy, 0);

    // s1: W-attention  |  s2: channel attention  |  default: tr -> H-attention -> tr
    k_att<false><<<dim3(128, 8), 512, SMEM_ATT, s1>>>(q_w, q_b, k_w, k_b, v_w, v_b);
    cudaEventRecord(evw, s1);
    k_c  <<<dim3(128, 8), 512, SMEM_C, s2>>>(cq_w, cq_b, ck_w, ck_b, cv_b);
    cudaEventRecord(evc, s2);

    k_tr <<<dim3(16, 64, 8), dim3(32, 8)>>>(py, pytr, 16384, 128, 128, 8192);
    k_att<true> <<<dim3(128, 8), 512, SMEM_ATT>>>(q_w, q_b, k_w, k_b, v_w, v_b);
    k_tr <<<dim3(16, 64, 8), dim3(32, 8)>>>(pytr, pOH, 128, 8192, 16384, 128);

    // join and finish
    cudaStreamWaitEvent(0, evw, 0);
    cudaStreamWaitEvent(0, evc, 0);
    k_final<<<dim3(64, 8), 256, SMEM_F>>>(gamma, sigma, out);
}

// round 17
// speedup vs baseline: 1.3132x; 1.0358x over previous
#include <cuda_runtime.h>
#include <math.h>

#define BB 8
#define CIN 256
#define CO 64
#define VV 128
#define TT 128
#define SY 132

__device__ float g_y  [BB*CO*VV*TT];
__device__ float g_ytr[BB*TT*CO*VV];   // y_tr, later reused as OH_tr
__device__ float g_OH [BB*CO*VV*TT];
__device__ float g_OW [BB*CO*VV*TT];
__device__ float g_av [BB*CO*VV*TT];   // pre-rounded tf32 bits (written by k_c)
__device__ float g_mH [BB*VV*TT];
__device__ float g_ZH [BB*VV*TT];
__device__ float g_mW [BB*VV*TT];
__device__ float g_ZW [BB*VV*TT];
__device__ float g_wtr[64*576];        // [ci][kk][o], tf32-rounded bits
__device__ float g_cvwt[64*64];        // cvw pre-rounded tf32 bits
__device__ float g_dwt[256*64];        // dc_w transposed [ci][o], fp32 exact

typedef unsigned long long u64;

__device__ __forceinline__ float4 ld4s(const float* p){ return *reinterpret_cast<const float4*>(p); }
__device__ __forceinline__ void st4s(float* p, float4 v){ *reinterpret_cast<float4*>(p) = v; }
__device__ __forceinline__ float4 ld4g(const float* p){ return __ldg(reinterpret_cast<const float4*>(p)); }
__device__ __forceinline__ ulonglong2 ld2x2s(const float* p){ return *reinterpret_cast<const ulonglong2*>(p); }
__device__ __forceinline__ void st2x2s(float* p, ulonglong2 v){ *reinterpret_cast<ulonglong2*>(p) = v; }
__device__ __forceinline__ u64 pk2(float x){ u64 r; asm("mov.b64 %0,{%1,%1};" : "=l"(r) : "f"(x)); return r; }
__device__ __forceinline__ float2 up2(u64 a){ float2 f; asm("mov.b64 {%0,%1},%2;" : "=f"(f.x), "=f"(f.y) : "l"(a)); return f; }
__device__ __forceinline__ u64 fma2(u64 a, u64 b, u64 c){
    u64 d; asm("fma.rn.f32x2 %0,%1,%2,%3;" : "=l"(d) : "l"(a), "l"(b), "l"(c)); return d;
}
__device__ __forceinline__ float dot4(float4 a, float4 b, float c){
    c = fmaf(a.x,b.x,c); c = fmaf(a.y,b.y,c); c = fmaf(a.z,b.z,c); return fmaf(a.w,b.w,c);
}
__device__ __forceinline__ unsigned tf32b(float x){
    unsigned u; asm("cvt.rna.tf32.f32 %0, %1;" : "=r"(u) : "f"(x)); return u;
}
__device__ __forceinline__ float rnd(float x){ return __uint_as_float(tf32b(x)); }
__device__ __forceinline__ unsigned fbits(float x){ return __float_as_uint(x); }
__device__ __forceinline__ void mma_tf32(float* d, unsigned a0, unsigned a1, unsigned a2, unsigned a3,
                                         unsigned b0, unsigned b1){
    asm("mma.sync.aligned.m16n8k8.row.col.f32.tf32.tf32.f32 "
        "{%0,%1,%2,%3}, {%4,%5,%6,%7}, {%8,%9}, {%0,%1,%2,%3};"
        : "+f"(d[0]), "+f"(d[1]), "+f"(d[2]), "+f"(d[3])
        : "r"(a0), "r"(a1), "r"(a2), "r"(a3), "r"(b0), "r"(b1));
}

// ---------------- prep: transpose dc_w -> g_dwt[ci][o] ----------------
__global__ __launch_bounds__(256) void k_wd(const float* __restrict__ w) {
    int i = blockIdx.x*256 + threadIdx.x;   // < 16384
    int ci = i >> 6, o = i & 63;
    g_dwt[i] = __ldg(w + (size_t)o*CIN + ci);
}

// ---------------- k_y: y = dc_w @ xp + dc_b ----------------
// 64-ci chunks, 4 CTAs/SM (forced <=64 regs), acc layout [t][o-pair]
__global__ __launch_bounds__(256, 4) void k_y(const float* __restrict__ x,
                                              const float* __restrict__ bias) {
    __shared__ float xs[64][128];
    __shared__ float wsT[64*64];   // [ci][o]
    int v = blockIdx.x, b = blockIdx.y;
    int tid = threadIdx.x, lane = tid & 31, warp = tid >> 5, t4 = lane*4;
    int o8 = warp * 8;
    ulonglong2 acc[4][2];
#pragma unroll
    for (int j = 0; j < 4; j++)
#pragma unroll
        for (int p = 0; p < 2; p++) { acc[j][p].x = 0ull; acc[j][p].y = 0ull; }
    bool vin = (v >= 1 && v <= 126);
    for (int c0 = 0; c0 < CIN; c0 += 64) {
        for (int i = tid; i < 64*128; i += 256) {
            int ci = i >> 7, t = i & 127;
            float val = 0.f;
            if (vin && t >= 1 && t <= 126)
                val = x[(((size_t)b*CIN + c0 + ci)*126 + (v-1))*126 + (t-1)];
            xs[ci][t] = val;
        }
        for (int i = tid; i < 1024; i += 256)
            st4s(wsT + i*4, ld4g(g_dwt + c0*64 + i*4));
        __syncthreads();
#pragma unroll 4
        for (int ci = 0; ci < 64; ci++) {
            float4 xv = ld4s(&xs[ci][t4]);
            u64 xp[4] = {pk2(xv.x), pk2(xv.y), pk2(xv.z), pk2(xv.w)};
            ulonglong2 wA = ld2x2s(wsT + ci*64 + o8);
            ulonglong2 wB = ld2x2s(wsT + ci*64 + o8 + 4);
#pragma unroll
            for (int j = 0; j < 4; j++) {
                acc[j][0].x = fma2(xp[j], wA.x, acc[j][0].x);
                acc[j][0].y = fma2(xp[j], wA.y, acc[j][0].y);
                acc[j][1].x = fma2(xp[j], wB.x, acc[j][1].x);
                acc[j][1].y = fma2(xp[j], wB.y, acc[j][1].y);
            }
        }
        __syncthreads();
    }
    float vals[4][8];
#pragma unroll
    for (int j = 0; j < 4; j++) {
        float2 a0 = up2(acc[j][0].x), a1 = up2(acc[j][0].y);
        float2 a2 = up2(acc[j][1].x), a3 = up2(acc[j][1].y);
        vals[j][0] = a0.x; vals[j][1] = a0.y; vals[j][2] = a1.x; vals[j][3] = a1.y;
        vals[j][4] = a2.x; vals[j][5] = a2.y; vals[j][6] = a3.x; vals[j][7] = a3.y;
    }
#pragma unroll
    for (int k = 0; k < 8; k++) {
        int o = o8 + k;
        float bo = __ldg(bias + o);
        st4s(&g_y[(((size_t)b*CO + o)*VV + v)*TT + t4],
             make_float4(vals[0][k]+bo, vals[1][k]+bo, vals[2][k]+bo, vals[3][k]+bo));
    }
}

// ------------- generic 128x128 transpose per (b,c) -------------
__global__ __launch_bounds__(256) void k_tr(const float* __restrict__ src,
                                            float* __restrict__ dst,
                                            int sc, int sr, int dc, int dq) {
    __shared__ float s[32][33];
    int tile = blockIdx.x, c = blockIdx.y, b = blockIdx.z;
    int r0 = (tile >> 2) * 32, q0 = (tile & 3) * 32;
    int tx = threadIdx.x, ty = threadIdx.y;
    const float* sp = src + (size_t)b*1048576 + (size_t)c*sc;
#pragma unroll
    for (int i = 0; i < 32; i += 8) s[ty+i][tx] = sp[(size_t)(r0+ty+i)*sr + q0 + tx];
    __syncthreads();
    float* dp = dst + (size_t)b*1048576 + (size_t)c*dc;
#pragma unroll
    for (int i = 0; i < 32; i += 8) dp[(size_t)(q0+ty+i)*dq + r0 + tx] = s[tx][ty+i];
}

// ---------------- weight transposes (tf32 pre-rounded) ----------------
__global__ __launch_bounds__(256) void k_wt(const float* __restrict__ avw) {
    int i = blockIdx.x*256 + threadIdx.x;   // < 36864
    int ci = i / 576, rem = i - ci*576;
    int kk = rem >> 6, o = rem & 63;
    g_wtr[i] = rnd(__ldg(avw + (size_t)o*576 + ci*9 + kk));
}
__global__ __launch_bounds__(256) void k_wv(const float* __restrict__ cvw) {
    int i = blockIdx.x*256 + threadIdx.x;   // < 4096
    g_cvwt[i] = rnd(__ldg(cvw + i));
}

// ------------- spatial attention (W / H) -------------
template<bool ISH>
__global__ __launch_bounds__(512, 2) void k_att(
    const float* __restrict__ qw, const float* __restrict__ qb,
    const float* __restrict__ kw, const float* __restrict__ kb,
    const float* __restrict__ vw, const float* __restrict__ vb) {
    int idx = blockIdx.x, b = blockIdx.y;
    int tid = threadIdx.x, lane = tid & 31, warp = tid >> 5, t4 = lane*4;
    extern __shared__ float sm[];
    float* E  = sm;              // E_T[s][t]
    float* ys = sm;              // alias rows 0..63
    float* qs = sm + 128*SY;
    float* ks = qs + 8*SY;
    float* vs = ks + 8*SY;       // stored tf32-pre-rounded
    float* pm = qs;
    float* pz = qs + 512;

    if (ISH) {
        const float* ysrc = g_ytr + (size_t)(b*TT + idx)*8192;
        for (int i = tid*4; i < 8192; i += 2048)
            st4s(ys + (i>>7)*SY + (i&127), ld4g(ysrc + i));
    } else {
        const float* ysrc = g_y + (size_t)b*1048576 + (size_t)idx*TT;
        for (int i = tid; i < 2048; i += 512) {
            int c = i >> 5, tt = (i & 31)*4;
            st4s(ys + c*SY + tt, ld4g(ysrc + (size_t)c*16384 + tt));
        }
    }
    __syncthreads();

    { // FUSED q/k/v projection: one pass over ys
        int c4 = warp * 4;
        int which = warp >> 3, cq = warp & 7;
        const float* Wqk = which ? kw : qw;
        ulonglong2 acc[4], qa;
#pragma unroll
        for (int i = 0; i < 4; i++) { u64 bp = pk2(__ldg(vb + c4 + i)); acc[i].x = bp; acc[i].y = bp; }
        { u64 bp = pk2(__ldg((which ? kb : qb) + cq)); qa.x = bp; qa.y = bp; }
#pragma unroll 2
        for (int cc = 0; cc < 64; cc += 4) {
            ulonglong2 y0 = ld2x2s(ys + (cc+0)*SY + t4);
            ulonglong2 y1 = ld2x2s(ys + (cc+1)*SY + t4);
            ulonglong2 y2 = ld2x2s(ys + (cc+2)*SY + t4);
            ulonglong2 y3 = ld2x2s(ys + (cc+3)*SY + t4);
            float4 wq = ld4g(Wqk + (size_t)cq*64 + cc);
            qa.x = fma2(pk2(wq.x), y0.x, qa.x); qa.y = fma2(pk2(wq.x), y0.y, qa.y);
            qa.x = fma2(pk2(wq.y), y1.x, qa.x); qa.y = fma2(pk2(wq.y), y1.y, qa.y);
            qa.x = fma2(pk2(wq.z), y2.x, qa.x); qa.y = fma2(pk2(wq.z), y2.y, qa.y);
            qa.x = fma2(pk2(wq.w), y3.x, qa.x); qa.y = fma2(pk2(wq.w), y3.y, qa.y);
#pragma unroll
            for (int i = 0; i < 4; i++) {
                float4 wv = ld4g(vw + (size_t)(c4+i)*64 + cc);
                acc[i].x = fma2(pk2(wv.x), y0.x, acc[i].x); acc[i].y = fma2(pk2(wv.x), y0.y, acc[i].y);
                acc[i].x = fma2(pk2(wv.y), y1.x, acc[i].x); acc[i].y = fma2(pk2(wv.y), y1.y, acc[i].y);
                acc[i].x = fma2(pk2(wv.z), y2.x, acc[i].x); acc[i].y = fma2(pk2(wv.z), y2.y, acc[i].y);
                acc[i].x = fma2(pk2(wv.w), y3.x, acc[i].x); acc[i].y = fma2(pk2(wv.w), y3.y, acc[i].y);
            }
        }
#pragma unroll
        for (int i = 0; i < 4; i++) {   // store vs pre-rounded to tf32 bits
            float2 lo = up2(acc[i].x), hi = up2(acc[i].y);
            st4s(vs + (c4+i)*SY + t4,
                 make_float4(rnd(lo.x), rnd(lo.y), rnd(hi.x), rnd(hi.y)));
        }
        st2x2s((which ? ks : qs) + cq*SY + t4, qa);   // q/k stay fp32-exact
    }
    __syncthreads();

    { // QK (f32x2) -> E_T[s][t]
        int s0 = (tid >> 4) * 4, t0 = (tid & 15) * 8;
        u64 acc[4][4];
#pragma unroll
        for (int i = 0; i < 4; i++)
#pragma unroll
            for (int j = 0; j < 4; j++) acc[i][j] = 0ull;
#pragma unroll
        for (int c = 0; c < 8; c++) {
            float kv[4];
#pragma unroll
            for (int i = 0; i < 4; i++) kv[i] = ks[c*SY + s0 + i];
            ulonglong2 qA = ld2x2s(qs + c*SY + t0);
            ulonglong2 qB = ld2x2s(qs + c*SY + t0 + 4);
#pragma unroll
            for (int i = 0; i < 4; i++) {
                u64 kp = pk2(kv[i]);
                acc[i][0] = fma2(kp, qA.x, acc[i][0]);
                acc[i][1] = fma2(kp, qA.y, acc[i][1]);
                acc[i][2] = fma2(kp, qB.x, acc[i][2]);
                acc[i][3] = fma2(kp, qB.y, acc[i][3]);
            }
        }
#pragma unroll
        for (int i = 0; i < 4; i++) {
            float2 p0 = up2(acc[i][0]), p1 = up2(acc[i][1]);
            float2 p2 = up2(acc[i][2]), p3 = up2(acc[i][3]);
            float vals[8] = {p0.x,p0.y,p1.x,p1.y,p2.x,p2.y,p3.x,p3.y};
            if (ISH) {
                int d = s0 + i - t0;
                if (d >= 0 && d < 8) vals[d] = -1e30f;
            }
            st4s(E + (s0+i)*SY + t0,   make_float4(vals[0],vals[1],vals[2],vals[3]));
            st4s(E + (s0+i)*SY + t0+4, make_float4(vals[4],vals[5],vals[6],vals[7]));
        }
    }
    __syncthreads();

    { // softmax over s per column t; stores PRE-ROUNDED p, Z from rounded p
        int t = tid & 127, q = tid >> 7;
        int sbeg = q * 32;
        float m = -INFINITY;
#pragma unroll 8
        for (int s = sbeg; s < sbeg + 32; s++) m = fmaxf(m, E[s*SY + t]);
        pm[q*128 + t] = m;
        __syncthreads();
        float M = fmaxf(fmaxf(pm[t], pm[128+t]), fmaxf(pm[256+t], pm[384+t]));
        float Z = 0.f;
#pragma unroll 8
        for (int s = sbeg; s < sbeg + 32; s++) {
            float p = rnd(__expf(E[s*SY + t] - M));
            E[s*SY + t] = p; Z += p;
        }
        pz[q*128 + t] = Z;
        __syncthreads();
        if (q == 0) {
            float Zt = pz[t] + pz[128+t] + pz[256+t] + pz[384+t];
            if (ISH) { g_mH[((size_t)b*VV + t)*TT + idx] = M; g_ZH[((size_t)b*VV + t)*TT + idx] = Zt; }
            else     { g_mW[((size_t)b*VV + idx)*TT + t] = M; g_ZW[((size_t)b*VV + idx)*TT + t] = Zt; }
        }
    }
    __syncthreads();

    { // apply via tf32 MMA, zero cvts (operands pre-rounded)
        int warpM = warp & 3, warpN = warp >> 2;
        int m0 = warpM * 16, n0 = warpN * 32;
        int g = lane >> 2, c = lane & 3;
        float d[4][4];
#pragma unroll
        for (int nt = 0; nt < 4; nt++)
#pragma unroll
            for (int j = 0; j < 4; j++) d[nt][j] = 0.f;
#pragma unroll 4
        for (int k0 = 0; k0 < 128; k0 += 8) {
            unsigned a0 = fbits(vs[(m0+g)*SY   + k0 + c]);
            unsigned a1 = fbits(vs[(m0+g+8)*SY + k0 + c]);
            unsigned a2 = fbits(vs[(m0+g)*SY   + k0 + c + 4]);
            unsigned a3 = fbits(vs[(m0+g+8)*SY + k0 + c + 4]);
#pragma unroll
            for (int nt = 0; nt < 4; nt++) {
                unsigned b0 = fbits(E[(k0+c)*SY   + n0 + nt*8 + g]);
                unsigned b1 = fbits(E[(k0+c+4)*SY + n0 + nt*8 + g]);
                mma_tf32(d[nt], a0, a1, a2, a3, b0, b1);
            }
        }
        if (ISH) {
            float* dst = g_ytr + (size_t)(b*TT + idx)*8192;
#pragma unroll
            for (int nt = 0; nt < 4; nt++) {
                int t = n0 + nt*8 + 2*c;
                *reinterpret_cast<float2*>(dst + (m0+g)*128 + t)   = make_float2(d[nt][0], d[nt][1]);
                *reinterpret_cast<float2*>(dst + (m0+g+8)*128 + t) = make_float2(d[nt][2], d[nt][3]);
            }
        } else {
            float* dst = g_OW + (size_t)b*1048576 + (size_t)idx*TT;
#pragma unroll
            for (int nt = 0; nt < 4; nt++) {
                int t = n0 + nt*8 + 2*c;
                *reinterpret_cast<float2*>(dst + (size_t)(m0+g)*16384 + t)   = make_float2(d[nt][0], d[nt][1]);
                *reinterpret_cast<float2*>(dst + (size_t)(m0+g+8)*16384 + t) = make_float2(d[nt][2], d[nt][3]);
            }
        }
    }
}

// ------------- channel attention per (b,v) -------------
__global__ __launch_bounds__(512, 2) void k_c(
    const float* __restrict__ cqw, const float* __restrict__ cqb,
    const float* __restrict__ ckw, const float* __restrict__ ckb,
    const float* __restrict__ cvb) {
    int v = blockIdx.x, b = blockIdx.y;
    int tid = threadIdx.x, lane = tid & 31, warp = tid >> 5, t4 = lane*4;
    extern __shared__ float sm[];
    float* ys = sm;
    float* qc = sm + 64*SY;
    float* kc = sm + 128*SY;
    float* bC = sm + 192*SY;
    float* Ec = kc;              // alias (pitch 68)
    float* M  = qc;              // alias (pitch 68)
    int c4 = warp * 4;
    int g = lane >> 2, cl = lane & 3;
    int warpM = warp & 3, warpN = warp >> 2;
    int m0 = warpM * 16;

    const float* ysrc = g_y + (size_t)b*1048576 + (size_t)v*TT;
    for (int i = tid; i < 2048; i += 512) {
        int c = i >> 5, tt = (i & 31)*4;
        st4s(ys + c*SY + tt, ld4g(ysrc + (size_t)c*16384 + tt));
    }
    __syncthreads();

    { // FUSED qc+kc projection (fp32-exact)
        ulonglong2 qa[4], ka[4];
#pragma unroll
        for (int i = 0; i < 4; i++) {
            u64 bq = pk2(__ldg(cqb + c4 + i)); qa[i].x = bq; qa[i].y = bq;
            u64 bk = pk2(__ldg(ckb + c4 + i)); ka[i].x = bk; ka[i].y = bk;
        }
#pragma unroll 2
        for (int cc = 0; cc < 64; cc += 2) {
            ulonglong2 y0 = ld2x2s(ys + (cc+0)*SY + t4);
            ulonglong2 y1 = ld2x2s(ys + (cc+1)*SY + t4);
#pragma unroll
            for (int i = 0; i < 4; i++) {
                float2 wq = __ldg(reinterpret_cast<const float2*>(cqw + (size_t)(c4+i)*64 + cc));
                float2 wk = __ldg(reinterpret_cast<const float2*>(ckw + (size_t)(c4+i)*64 + cc));
                qa[i].x = fma2(pk2(wq.x), y0.x, qa[i].x); qa[i].y = fma2(pk2(wq.x), y0.y, qa[i].y);
                qa[i].x = fma2(pk2(wq.y), y1.x, qa[i].x); qa[i].y = fma2(pk2(wq.y), y1.y, qa[i].y);
                ka[i].x = fma2(pk2(wk.x), y0.x, ka[i].x); ka[i].y = fma2(pk2(wk.x), y0.y, ka[i].y);
                ka[i].x = fma2(pk2(wk.y), y1.x, ka[i].x); ka[i].y = fma2(pk2(wk.y), y1.y, ka[i].y);
            }
        }
#pragma unroll
        for (int i = 0; i < 4; i++) {
            st2x2s(qc + (c4+i)*SY + t4, qa[i]);
            st2x2s(kc + (c4+i)*SY + t4, ka[i]);
        }
    }
    __syncthreads();

    { // Ec = qc*kc^T via 3xtf32 MMA (fp32-accurate energies)
        int n0 = warpN * 16;
        float d2[2][4];
#pragma unroll
        for (int nt = 0; nt < 2; nt++)
#pragma unroll
            for (int j = 0; j < 4; j++) d2[nt][j] = 0.f;
#pragma unroll 2
        for (int k0 = 0; k0 < 128; k0 += 8) {
            float af0 = qc[(m0+g)*SY   + k0 + cl];
            float af1 = qc[(m0+g+8)*SY + k0 + cl];
            float af2 = qc[(m0+g)*SY   + k0 + cl + 4];
            float af3 = qc[(m0+g+8)*SY + k0 + cl + 4];
            unsigned ah0 = tf32b(af0), ah1 = tf32b(af1), ah2 = tf32b(af2), ah3 = tf32b(af3);
            unsigned al0 = tf32b(af0 - __uint_as_float(ah0));
            unsigned al1 = tf32b(af1 - __uint_as_float(ah1));
            unsigned al2 = tf32b(af2 - __uint_as_float(ah2));
            unsigned al3 = tf32b(af3 - __uint_as_float(ah3));
#pragma unroll
            for (int nt = 0; nt < 2; nt++) {
                float bf0 = kc[(n0 + nt*8 + g)*SY + k0 + cl];
                float bf1 = kc[(n0 + nt*8 + g)*SY + k0 + cl + 4];
                unsigned bh0 = tf32b(bf0), bh1 = tf32b(bf1);
                unsigned bl0 = tf32b(bf0 - __uint_as_float(bh0));
                unsigned bl1 = tf32b(bf1 - __uint_as_float(bh1));
                mma_tf32(d2[nt], ah0, ah1, ah2, ah3, bh0, bh1);
                mma_tf32(d2[nt], ah0, ah1, ah2, ah3, bl0, bl1);
                mma_tf32(d2[nt], al0, al1, al2, al3, bh0, bh1);
            }
        }
        __syncthreads();
#pragma unroll
        for (int nt = 0; nt < 2; nt++) {
            int dd = n0 + nt*8 + 2*cl;
            *reinterpret_cast<float2*>(Ec + (m0+g)*68 + dd)   = make_float2(d2[nt][0], d2[nt][1]);
            *reinterpret_cast<float2*>(Ec + (m0+g+8)*68 + dd) = make_float2(d2[nt][2], d2[nt][3]);
        }
    }
    __syncthreads();

    { // softmax rows of Ec (8 threads/row); store pre-rounded weights
        int r = tid >> 3, sub = tid & 7;
        float* row = Ec + r*68;
        float4 x0 = ld4s(row + sub*4), x1 = ld4s(row + sub*4 + 32);
        float m = fmaxf(fmaxf(fmaxf(x0.x,x0.y),fmaxf(x0.z,x0.w)),
                        fmaxf(fmaxf(x1.x,x1.y),fmaxf(x1.z,x1.w)));
        m = fmaxf(m, __shfl_xor_sync(~0u, m, 1));
        m = fmaxf(m, __shfl_xor_sync(~0u, m, 2));
        m = fmaxf(m, __shfl_xor_sync(~0u, m, 4));
        x0.x=__expf(x0.x-m); x0.y=__expf(x0.y-m); x0.z=__expf(x0.z-m); x0.w=__expf(x0.w-m);
        x1.x=__expf(x1.x-m); x1.y=__expf(x1.y-m); x1.z=__expf(x1.z-m); x1.w=__expf(x1.w-m);
        float Z = x0.x+x0.y+x0.z+x0.w + x1.x+x1.y+x1.z+x1.w;
        Z += __shfl_xor_sync(~0u, Z, 1);
        Z += __shfl_xor_sync(~0u, Z, 2);
        Z += __shfl_xor_sync(~0u, Z, 4);
        float inv = 1.f / Z;
        x0.x = rnd(x0.x*inv); x0.y = rnd(x0.y*inv); x0.z = rnd(x0.z*inv); x0.w = rnd(x0.w*inv);
        x1.x = rnd(x1.x*inv); x1.y = rnd(x1.y*inv); x1.z = rnd(x1.z*inv); x1.w = rnd(x1.w*inv);
        st4s(row + sub*4, x0); st4s(row + sub*4 + 32, x1);
    }
    __syncthreads();

    if (tid < 64) {   // bC = attn @ cvb
        float a = 0.f;
        for (int d = 0; d < 64; d++) a = fmaf(Ec[tid*68 + d], __ldg(cvb + d), a);
        bC[tid] = a;
    }
    float dM[2][4];
    { // M = attn @ cvw via tf32 MMA, zero cvts
        int n0 = warpN * 16;
#pragma unroll
        for (int nt = 0; nt < 2; nt++)
#pragma unroll
            for (int j = 0; j < 4; j++) dM[nt][j] = 0.f;
#pragma unroll
        for (int k0 = 0; k0 < 64; k0 += 8) {
            unsigned a0 = fbits(Ec[(m0+g)*68   + k0 + cl]);
            unsigned a1 = fbits(Ec[(m0+g+8)*68 + k0 + cl]);
            unsigned a2 = fbits(Ec[(m0+g)*68   + k0 + cl + 4]);
            unsigned a3 = fbits(Ec[(m0+g+8)*68 + k0 + cl + 4]);
#pragma unroll
            for (int nt = 0; nt < 2; nt++) {
                unsigned b0 = fbits(__ldg(g_cvwt + (size_t)(k0+cl)*64   + n0 + nt*8 + g));
                unsigned b1 = fbits(__ldg(g_cvwt + (size_t)(k0+cl+4)*64 + n0 + nt*8 + g));
                mma_tf32(dM[nt], a0, a1, a2, a3, b0, b1);
            }
        }
    }
    __syncthreads();
    {   // store M pre-rounded
        int n0 = warpN * 16;
#pragma unroll
        for (int nt = 0; nt < 2; nt++) {
            int e = n0 + nt*8 + 2*cl;
            *reinterpret_cast<float2*>(M + (m0+g)*68 + e)   = make_float2(rnd(dM[nt][0]), rnd(dM[nt][1]));
            *reinterpret_cast<float2*>(M + (m0+g+8)*68 + e) = make_float2(rnd(dM[nt][2]), rnd(dM[nt][3]));
        }
    }
    __syncthreads();

    { // av = M @ ys + bC via tf32 MMA; store av PRE-ROUNDED
        int n0 = warpN * 32;
        float d4[4][4];
        float b0v = bC[m0+g], b1v = bC[m0+g+8];
#pragma unroll
        for (int nt = 0; nt < 4; nt++) {
            d4[nt][0] = b0v; d4[nt][1] = b0v;
            d4[nt][2] = b1v; d4[nt][3] = b1v;
        }
#pragma unroll
        for (int k0 = 0; k0 < 64; k0 += 8) {
            unsigned a0 = fbits(M[(m0+g)*68   + k0 + cl]);
            unsigned a1 = fbits(M[(m0+g+8)*68 + k0 + cl]);
            unsigned a2 = fbits(M[(m0+g)*68   + k0 + cl + 4]);
            unsigned a3 = fbits(M[(m0+g+8)*68 + k0 + cl + 4]);
#pragma unroll
            for (int nt = 0; nt < 4; nt++) {
                unsigned b0 = tf32b(ys[(k0+cl)*SY   + n0 + nt*8 + g]);
                unsigned b1 = tf32b(ys[(k0+cl+4)*SY + n0 + nt*8 + g]);
                mma_tf32(d4[nt], a0, a1, a2, a3, b0, b1);
            }
        }
        float* dst = g_av + (size_t)b*1048576 + (size_t)v*TT;
#pragma unroll
        for (int nt = 0; nt < 4; nt++) {
            int t = n0 + nt*8 + 2*cl;
            *reinterpret_cast<float2*>(dst + (size_t)(m0+g)*16384 + t)   = make_float2(rnd(d4[nt][0]), rnd(d4[nt][1]));
            *reinterpret_cast<float2*>(dst + (size_t)(m0+g+8)*16384 + t) = make_float2(rnd(d4[nt][2]), rnd(d4[nt][3]));
        }
    }
}

// ------------- k_final: tf32 mma 3x3 conv + recombine -------------
#define AVR 20
#define AVC 360          // 18*AVR
#define CSP 260          // convS pitch, multiple of 4
__global__ __launch_bounds__(256, 2) void k_final(
    const float* __restrict__ gamma_p, const float* __restrict__ sigma_p,
    float* __restrict__ out) {
    extern __shared__ float smf[];
    float* avs = smf;                 // [16 ci][18 rows][AVR] (pre-rounded values)
    float* wss = smf + 16*AVC;        // [16 ci][9 kk][64 o]  (pre-rounded)
    float* convS = smf;               // alias after mma: [64 o][CSP]
    float* scS = smf + 64*CSP;        // [2][256] scales
    int b = blockIdx.y, tile = blockIdx.x;
    int v0 = (tile >> 3) * 16, t0 = (tile & 7) * 16;
    int tid = threadIdx.x, lane = tid & 31, warp = tid >> 5;
    int g = lane >> 2, c = lane & 3;
    int warpM = warp >> 1, warpN = warp & 1;

    float d[16][4];
#pragma unroll
    for (int i = 0; i < 16; i++)
#pragma unroll
        for (int j = 0; j < 4; j++) d[i][j] = 0.f;

    for (int chunk = 0; chunk < 4; chunk++) {
        int ci0 = chunk * 16;
        __syncthreads();
        for (int i = tid; i < 16*324; i += 256) {
            int ci = i / 324, rr = i - ci*324;
            int r = rr / 18, cc = rr - r*18;
            int vv = v0 - 1 + r, t = t0 - 1 + cc;
            float val = 0.f;
            if (vv >= 0 && vv < 128 && t >= 0 && t < 128)
                val = g_av[(size_t)(b*64 + ci0 + ci)*16384 + (size_t)vv*128 + t];
            avs[ci*AVC + r*AVR + cc] = val;
        }
        for (int i = tid; i < 16*576; i += 256)
            wss[i] = g_wtr[ci0*576 + i];
        __syncthreads();

        const unsigned* wsu = reinterpret_cast<const unsigned*>(wss);
#pragma unroll
        for (int kk = 0; kk < 9; kk++) {
            int dv = kk / 3, dt = kk - dv*3;
#pragma unroll
            for (int ks = 0; ks < 2; ks++) {
                const unsigned* wp = wsu + (ks*8 + c)*576 + kk*64 + warpM*16 + g;
                unsigned a0 = wp[0], a1 = wp[8];
                unsigned a2 = wp[4*576], a3 = wp[4*576 + 8];
                int cb0 = (ks*8 + c)*AVC + dv*AVR + dt;
#pragma unroll
                for (int nt = 0; nt < 16; nt++) {
                    int pr = warpN*8 + (nt >> 1);
                    int pc = (nt & 1)*8 + g;
                    unsigned f0 = fbits(avs[cb0 + pr*AVR + pc]);
                    unsigned f1 = fbits(avs[cb0 + 4*AVC + pr*AVR + pc]);
                    mma_tf32(d[nt], a0, a1, a2, a3, f0, f1);
                }
            }
        }
    }
    __syncthreads();

#pragma unroll
    for (int nt = 0; nt < 16; nt++) {
        int pr = warpN*8 + (nt >> 1);
        int pc = (nt & 1)*8 + 2*c;
        int pix = pr*16 + pc;
        int o = warpM*16 + g;
        *reinterpret_cast<float2*>(convS + o*CSP + pix)     = make_float2(d[nt][0], d[nt][1]);
        *reinterpret_cast<float2*>(convS + (o+8)*CSP + pix) = make_float2(d[nt][2], d[nt][3]);
    }
    {
        float gamma = __ldg(gamma_p);
        int v = v0 + (tid >> 4), t = t0 + (tid & 15);
        size_t sidx = ((size_t)b*VV + v)*TT + t;
        float mH = __ldg(&g_mH[sidx]), ZH = __ldg(&g_ZH[sidx]);
        float mW = __ldg(&g_mW[sidx]), ZW = __ldg(&g_ZW[sidx]);
        float m = fmaxf(mH, mW);
        float eH = __expf(mH - m), eW = __expf(mW - m);
        float inv = gamma / (ZH*eH + ZW*eW);
        scS[tid]       = eH * inv;
        scS[256 + tid] = eW * inv;
    }
    __syncthreads();

    float sigma = __ldg(sigma_p);
    int o8 = warp * 8;
    int c4p = c * 4;
#pragma unroll
    for (int half = 0; half < 2; half++) {
        int rr = g + half*8;
        int pix = rr*16 + c4p;
        float sH0 = scS[pix],   sH1 = scS[pix+1],   sH2 = scS[pix+2],   sH3 = scS[pix+3];
        float sW0 = scS[256+pix], sW1 = scS[256+pix+1], sW2 = scS[256+pix+2], sW3 = scS[256+pix+3];
        int v = v0 + rr, t = t0 + c4p;
#pragma unroll
        for (int oi = 0; oi < 8; oi++) {
            int o = o8 + oi;
            size_t oidx = (((size_t)b*CO + o)*VV + v)*TT + t;
            float4 cv = ld4s(convS + o*CSP + pix);
            float4 yv = ld4g(&g_y[oidx]);
            float4 oh = ld4g(&g_OH[oidx]);
            float4 ow = ld4g(&g_OW[oidx]);
            float4 r;
            r.x = yv.x + sH0*oh.x + sW0*ow.x + sigma*cv.x;
            r.y = yv.y + sH1*oh.y + sW1*ow.y + sigma*cv.y;
            r.z = yv.z + sH2*oh.z + sW2*ow.z + sigma*cv.z;
            r.w = yv.w + sH3*oh.w + sW3*ow.w + sigma*cv.w;
            *reinterpret_cast<float4*>(out + oidx) = r;
        }
    }
}

// ---------------- launch: stream-parallel DAG ----------------
extern "C" void kernel_launch(void* const* d_in, const int* in_sizes, int n_in,
                              void* d_out, int out_size) {
    (void)in_sizes; (void)n_in; (void)out_size;
    const float* x    = (const float*)d_in[0];
    const float* dc_w = (const float*)d_in[1];
    const float* dc_b = (const float*)d_in[2];
    const float* q_w  = (const float*)d_in[3];
    const float* q_b  = (const float*)d_in[4];
    const float* k_w  = (const float*)d_in[5];
    const float* k_b  = (const float*)d_in[6];
    const float* v_w  = (const float*)d_in[7];
    const float* v_b  = (const float*)d_in[8];
    const float* gamma= (const float*)d_in[9];
    const float* cq_w = (const float*)d_in[10];
    const float* cq_b = (const float*)d_in[11];
    const float* ck_w = (const float*)d_in[12];
    const float* ck_b = (const float*)d_in[13];
    const float* cv_w = (const float*)d_in[14];
    const float* cv_b = (const float*)d_in[15];
    const float* av_w = (const float*)d_in[16];
    const float* sigma= (const float*)d_in[17];
    float* out = (float*)d_out;

    float *py, *pytr, *pOH;
    cudaGetSymbolAddress((void**)&py,   g_y);
    cudaGetSymbolAddress((void**)&pytr, g_ytr);
    cudaGetSymbolAddress((void**)&pOH,  g_OH);

    const int SMEM_ATT = 208*SY*4;                  // 109,824 B
    const int SMEM_C   = (192*SY + 64)*4;           // 101,632 B
    const int SMEM_F   = (64*CSP + 512)*4;          // 68,608 B

    static cudaStream_t s1 = nullptr, s2 = nullptr;
    static cudaEvent_t evy = nullptr, evw = nullptr, evc = nullptr;
    if (!s1) {
        cudaFuncSetAttribute(k_att<false>, cudaFuncAttributeMaxDynamicSharedMemorySize, SMEM_ATT);
        cudaFuncSetAttribute(k_att<true>,  cudaFuncAttributeMaxDynamicSharedMemorySize, SMEM_ATT);
        cudaFuncSetAttribute(k_c,          cudaFuncAttributeMaxDynamicSharedMemorySize, SMEM_C);
        cudaFuncSetAttribute(k_final,      cudaFuncAttributeMaxDynamicSharedMemorySize, SMEM_F);
        cudaStreamCreateWithFlags(&s1, cudaStreamNonBlocking);
        cudaStreamCreateWithFlags(&s2, cudaStreamNonBlocking);
        cudaEventCreateWithFlags(&evy, cudaEventDisableTiming);
        cudaEventCreateWithFlags(&evw, cudaEventDisableTiming);
        cudaEventCreateWithFlags(&evc, cudaEventDisableTiming);
    }

    // independent prologue on s1
    k_wt <<<144, 256, 0, s1>>>(av_w);
    k_wv <<<16, 256, 0, s1>>>(cv_w);

    // default stream: weight transpose, k_y, then fork
    k_wd <<<64, 256>>>(dc_w);
    k_y  <<<dim3(128, 8), 256>>>(x, dc_b);
    cudaEventRecord(evy, 0);
    cudaStreamWaitEvent(s1, evy, 0);
    cudaStreamWaitEvent(s2, evy, 0);

    // s1: W-attention  |  s2: channel attention  |  default: tr -> H-attention -> tr
    k_att<false><<<dim3(128, 8), 512, SMEM_ATT, s1>>>(q_w, q_b, k_w, k_b, v_w, v_b);
    cudaEventRecord(evw, s1);
    k_c  <<<dim3(128, 8), 512, SMEM_C, s2>>>(cq_w, cq_b, ck_w, ck_b, cv_b);
    cudaEventRecord(evc, s2);

    k_tr <<<dim3(16, 64, 8), dim3(32, 8)>>>(py, pytr, 16384, 128, 128, 8192);
    k_att<true> <<<dim3(128, 8), 512, SMEM_ATT>>>(q_w, q_b, k_w, k_b, v_w, v_b);
    k_tr <<<dim3(16, 64, 8), dim3(32, 8)>>>(pytr, pOH, 128, 8192, 16384, 128);

    // join and finish
    cudaStreamWaitEvent(0, evw, 0);
    cudaStreamWaitEvent(0, evc, 0);
    k_final<<<dim3(64, 8), 256, SMEM_F>>>(gamma, sigma, out);
}